// round 9
// baseline (speedup 1.0000x reference)
#include <cuda_runtime.h>
#include <cuda_bf16.h>
#include <math.h>
#include <stdint.h>

// ---------------- problem constants ----------------
#define NTOK (2*8*128*128)          // 262144 tokens
#define NWIN (NTOK/128)             // 2048 windows
#define SCALE 0.25f

// ---------------- scratch ----------------
__device__ __nv_bfloat16 g_wb [110592];              // bf16 weights

#define WB_QKV  0
#define WB_PROJ 27648
#define WB_FC1  36864
#define WB_FC2  73728

static __device__ __forceinline__ uint32_t s2u(const void* p) {
    return (uint32_t)__cvta_generic_to_shared(p);
}

#define LDSM_X4(r0,r1,r2,r3,addr) \
    asm volatile("ldmatrix.sync.aligned.m8n8.x4.shared.b16 {%0,%1,%2,%3}, [%4];" \
        : "=r"(r0),"=r"(r1),"=r"(r2),"=r"(r3) : "r"(addr))

#define LDSM_X4_T(r0,r1,r2,r3,addr) \
    asm volatile("ldmatrix.sync.aligned.m8n8.x4.trans.shared.b16 {%0,%1,%2,%3}, [%4];" \
        : "=r"(r0),"=r"(r1),"=r"(r2),"=r"(r3) : "r"(addr))

#define MMA_BF16(c,a0,a1,a2,a3,b0,b1) \
    asm volatile("mma.sync.aligned.m16n8k16.row.col.f32.bf16.bf16.f32 " \
        "{%0,%1,%2,%3},{%4,%5,%6,%7},{%8,%9},{%0,%1,%2,%3};" \
        : "+f"(c[0]),"+f"(c[1]),"+f"(c[2]),"+f"(c[3]) \
        : "r"(a0),"r"(a1),"r"(a2),"r"(a3),"r"(b0),"r"(b1))

// ---------------- weight conversion fp32 -> bf16 ----------------
__global__ void convert_w(const float* __restrict__ wq, const float* __restrict__ wp,
                          const float* __restrict__ w1, const float* __restrict__ w2,
                          __nv_bfloat16* __restrict__ out)
{
    int i = blockIdx.x * 256 + threadIdx.x;
    if (i < 27648)       out[i] = __float2bfloat16(wq[i]);
    else if (i < 36864)  out[i] = __float2bfloat16(wp[i - 27648]);
    else if (i < 73728)  out[i] = __float2bfloat16(w1[i - 36864]);
    else if (i < 110592) out[i] = __float2bfloat16(w2[i - 73728]);
}

// ================= MONO kernel: entire Swin block, one CTA per window =================
// smem layout (bf16 element offsets):
//   sA   [0,      13312)  128x104  LN1 out / attn out / LN2 out
//   sW   [13312,  43264)  288x104  Wqkv -> Wproj -> W1 halves (192x104) -> W2 halves (96x200)
//   sQKV [43264,  81152)  128x296  qkv; then y as fp32 128x100 (25600 elems)
//   sHID [68864,  94464)  128x200  MLP hidden half (reuses dead qkv tail)
//   lab  [94464,  94720)  128 ints
#define S_A    0
#define S_W    13312
#define S_QKV  43264
#define S_HID  68864
#define S_LAB  94464
#define SMEM_MONO ((S_LAB + 256) * 2)

__global__ __launch_bounds__(768, 1) void mono_kernel(
    const float* __restrict__ x,
    const float* __restrict__ g1, const float* __restrict__ b1,
    const __nv_bfloat16* __restrict__ wqkv, const float* __restrict__ b_qkv,
    const __nv_bfloat16* __restrict__ wproj, const float* __restrict__ b_proj,
    const float* __restrict__ g2, const float* __restrict__ b2,
    const __nv_bfloat16* __restrict__ w1, const float* __restrict__ bias1,
    const __nv_bfloat16* __restrict__ w2, const float* __restrict__ bias2,
    float* __restrict__ out)
{
    extern __shared__ __align__(16) char smem_raw[];
    __nv_bfloat16* sA   = (__nv_bfloat16*)smem_raw;
    __nv_bfloat16* sW   = sA + S_W;
    __nv_bfloat16* sQKV = sA + S_QKV;
    __nv_bfloat16* sHID = sA + S_HID;
    int*   lab = (int*)(sA + S_LAB);
    float* yep = (float*)sQKV;    // proj staging then y (fp32 128x100)

    const int win  = blockIdx.x;
    const int tid  = threadIdx.x;
    const int lane = tid & 31;
    const int warp = tid >> 5;

    const int wr = win & 1023;
    const int tb = wr >> 8, hb = (wr >> 4) & 15, wb = wr & 15;
    const int bi = win >> 10;

    // ---- phase 0: labels + Wqkv load + LN1 (shift gather) ----
    if (tid < 128) {
        int n = tid;
        int lt = (tb == 3) ? (n >> 6) : 0;
        int lh = (hb == 15) ? ((n >> 5) & 1) : 0;
        int lw = (wb == 15) ? ((n >> 2) & 1) : 0;
        lab[n] = lt | (lh << 1) | (lw << 2);
    }
    for (int gi = tid; gi < 3456; gi += 768) {
        int row = gi / 12, q = gi - row * 12;
        *(uint4*)(sW + row * 104 + q * 8) = *(const uint4*)(wqkv + (size_t)row * 96 + q * 8);
    }
    for (int tok = warp; tok < 128; tok += 24) {
        int dt = tok >> 6, dh = (tok >> 3) & 7, dw = tok & 7;
        int t = tb * 2 + dt, h = hb * 8 + dh, w = wb * 8 + dw;
        int ti = (t + 1) & 7, hi = (h + 4) & 127, wi = (w + 4) & 127;
        size_t src = ((size_t)((bi * 8 + ti) * 128 + hi)) * 128 + wi;
        const float* row = x + src * 96;
        float v0 = row[lane], v1 = row[lane + 32], v2 = row[lane + 64];
        float s  = v0 + v1 + v2;
        float s2 = v0 * v0 + v1 * v1 + v2 * v2;
        #pragma unroll
        for (int o = 16; o; o >>= 1) {
            s  += __shfl_xor_sync(0xffffffffu, s,  o);
            s2 += __shfl_xor_sync(0xffffffffu, s2, o);
        }
        float mean = s * (1.0f / 96.0f);
        float var  = s2 * (1.0f / 96.0f) - mean * mean;
        float rstd = rsqrtf(var + 1e-5f);
        __nv_bfloat16* orow = sA + tok * 104;
        orow[lane]      = __float2bfloat16((v0 - mean) * rstd * g1[lane]      + b1[lane]);
        orow[lane + 32] = __float2bfloat16((v1 - mean) * rstd * g1[lane + 32] + b1[lane + 32]);
        orow[lane + 64] = __float2bfloat16((v2 - mean) * rstd * g1[lane + 64] + b1[lane + 64]);
    }
    __syncthreads();

    // ---- phase 1: QKV GEMM -> sQKV (+bias, bf16) ----
    {
        const int wm = warp & 3, wn = warp >> 2;   // 4m x 6n
        float acc[2][6][4] = {};
        const uint32_t a0 = s2u(sA + (wm * 32 + (lane & 15)) * 104 + (lane >> 4) * 8);
        const uint32_t b0 = s2u(sW + (wn * 48 + ((lane >> 4) << 3) + (lane & 7)) * 104
                                   + ((lane >> 3) & 1) * 8);
        #pragma unroll
        for (int ks = 0; ks < 6; ks++) {
            uint32_t a[2][4], bf[3][4];
            #pragma unroll
            for (int mt = 0; mt < 2; mt++)
                LDSM_X4(a[mt][0], a[mt][1], a[mt][2], a[mt][3],
                        a0 + mt * (16 * 104 * 2) + ks * 32);
            #pragma unroll
            for (int ng = 0; ng < 3; ng++)
                LDSM_X4(bf[ng][0], bf[ng][1], bf[ng][2], bf[ng][3],
                        b0 + ng * (16 * 104 * 2) + ks * 32);
            #pragma unroll
            for (int mt = 0; mt < 2; mt++)
                #pragma unroll
                for (int nt = 0; nt < 6; nt++) {
                    int ng = nt >> 1, pr = (nt & 1) * 2;
                    MMA_BF16(acc[mt][nt], a[mt][0], a[mt][1], a[mt][2], a[mt][3],
                             bf[ng][pr], bf[ng][pr + 1]);
                }
        }
        #pragma unroll
        for (int mt = 0; mt < 2; mt++)
            #pragma unroll
            for (int nt = 0; nt < 6; nt++) {
                int row = wm * 32 + mt * 16 + (lane >> 2);
                int col = wn * 48 + nt * 8 + (lane & 3) * 2;
                float bf0 = b_qkv[col], bf1 = b_qkv[col + 1];
                __nv_bfloat162 p0, p1;
                p0.x = __float2bfloat16(acc[mt][nt][0] + bf0);
                p0.y = __float2bfloat16(acc[mt][nt][1] + bf1);
                p1.x = __float2bfloat16(acc[mt][nt][2] + bf0);
                p1.y = __float2bfloat16(acc[mt][nt][3] + bf1);
                *(__nv_bfloat162*)(sQKV + row * 296 + col)       = p0;
                *(__nv_bfloat162*)(sQKV + (row + 8) * 296 + col) = p1;
            }
    }
    __syncthreads();

    // ---- phase 2: attention (6 heads x 4 warps) + Wproj prefetch ----
    for (int gi = tid; gi < 1152; gi += 768) {
        int row = gi / 12, q = gi - row * 12;
        *(uint4*)(sW + row * 104 + q * 8) = *(const uint4*)(wproj + (size_t)row * 96 + q * 8);
    }
    {
        const int head = warp >> 2;
        const int warpRow = (warp & 3) * 32;
        const int hoff = head * 16;
        const bool masked = (tb == 3) || (hb == 15) || (wb == 15);

        #pragma unroll
        for (int mt = 0; mt < 2; mt++) {
            const int rbase = warpRow + mt * 16 + (lane >> 2);
            uint32_t qa[4];
            {
                uint32_t qaddr = s2u(sQKV + (warpRow + mt * 16 + (lane & 15)) * 296
                                          + hoff + (lane >> 4) * 8);
                LDSM_X4(qa[0], qa[1], qa[2], qa[3], qaddr);
            }
            const int lr0 = lab[rbase];
            const int lr1 = lab[rbase + 8];

            float sum0 = 0.0f, sum1 = 0.0f;
            uint32_t p[16][2];

            const uint32_t kaddr0 = s2u(sQKV + (((lane >> 4) << 3) + (lane & 7)) * 296
                                             + 96 + hoff + ((lane >> 3) & 1) * 8);
            #pragma unroll
            for (int j2 = 0; j2 < 8; j2++) {
                uint32_t kb[4];
                LDSM_X4(kb[0], kb[1], kb[2], kb[3], kaddr0 + j2 * (16 * 296 * 2));
                float c0[4] = {}, c1[4] = {};
                MMA_BF16(c0, qa[0], qa[1], qa[2], qa[3], kb[0], kb[1]);
                MMA_BF16(c1, qa[0], qa[1], qa[2], qa[3], kb[2], kb[3]);
                #pragma unroll
                for (int half = 0; half < 2; half++) {
                    float* c = half ? c1 : c0;
                    int j = 2 * j2 + half;
                    int col0 = j * 8 + (lane & 3) * 2;
                    float e00 = __expf(SCALE * c[0]);
                    float e01 = __expf(SCALE * c[1]);
                    float e10 = __expf(SCALE * c[2]);
                    float e11 = __expf(SCALE * c[3]);
                    if (masked) {
                        int lc0 = lab[col0], lc1 = lab[col0 + 1];
                        e00 = (lc0 == lr0) ? e00 : 0.0f;
                        e01 = (lc1 == lr0) ? e01 : 0.0f;
                        e10 = (lc0 == lr1) ? e10 : 0.0f;
                        e11 = (lc1 == lr1) ? e11 : 0.0f;
                    }
                    __nv_bfloat162 lo = __floats2bfloat162_rn(e00, e01);
                    __nv_bfloat162 hi = __floats2bfloat162_rn(e10, e11);
                    sum0 += __low2float(lo) + __high2float(lo);
                    sum1 += __low2float(hi) + __high2float(hi);
                    p[j][0] = *(uint32_t*)&lo;
                    p[j][1] = *(uint32_t*)&hi;
                }
            }
            sum0 += __shfl_xor_sync(0xffffffffu, sum0, 1);
            sum0 += __shfl_xor_sync(0xffffffffu, sum0, 2);
            sum1 += __shfl_xor_sync(0xffffffffu, sum1, 1);
            sum1 += __shfl_xor_sync(0xffffffffu, sum1, 2);
            float inv0 = 1.0f / sum0;
            float inv1 = 1.0f / sum1;

            float o[2][4] = {};
            const uint32_t vaddr0 = s2u(sQKV + (lane & 15) * 296 + 192 + hoff + (lane >> 4) * 8);
            #pragma unroll
            for (int kc = 0; kc < 8; kc++) {
                uint32_t vb[4];
                LDSM_X4_T(vb[0], vb[1], vb[2], vb[3], vaddr0 + kc * (16 * 296 * 2));
                MMA_BF16(o[0], p[2*kc][0], p[2*kc][1], p[2*kc+1][0], p[2*kc+1][1], vb[0], vb[1]);
                MMA_BF16(o[1], p[2*kc][0], p[2*kc][1], p[2*kc+1][0], p[2*kc+1][1], vb[2], vb[3]);
            }
            #pragma unroll
            for (int nt = 0; nt < 2; nt++) {
                int col = hoff + nt * 8 + (lane & 3) * 2;
                __nv_bfloat162 w0 = __floats2bfloat162_rn(o[nt][0] * inv0, o[nt][1] * inv0);
                __nv_bfloat162 w1 = __floats2bfloat162_rn(o[nt][2] * inv1, o[nt][3] * inv1);
                *(__nv_bfloat162*)(sA + rbase * 104 + col)       = w0;
                *(__nv_bfloat162*)(sA + (rbase + 8) * 104 + col) = w1;
            }
        }
    }
    __syncthreads();

    // ---- phase 3: proj GEMM -> yep staging (fp32 +bias) ----
    {
        const int wm = warp & 3, wn = warp >> 2;
        float acc[2][2][4] = {};
        const uint32_t a0 = s2u(sA + (wm * 32 + (lane & 15)) * 104 + (lane >> 4) * 8);
        const uint32_t b0 = s2u(sW + (wn * 16 + ((lane >> 4) << 3) + (lane & 7)) * 104
                                   + ((lane >> 3) & 1) * 8);
        #pragma unroll
        for (int ks = 0; ks < 6; ks++) {
            uint32_t a[2][4], kb[4];
            #pragma unroll
            for (int mt = 0; mt < 2; mt++)
                LDSM_X4(a[mt][0], a[mt][1], a[mt][2], a[mt][3],
                        a0 + mt * (16 * 104 * 2) + ks * 32);
            LDSM_X4(kb[0], kb[1], kb[2], kb[3], b0 + ks * 32);
            #pragma unroll
            for (int mt = 0; mt < 2; mt++) {
                MMA_BF16(acc[mt][0], a[mt][0], a[mt][1], a[mt][2], a[mt][3], kb[0], kb[1]);
                MMA_BF16(acc[mt][1], a[mt][0], a[mt][1], a[mt][2], a[mt][3], kb[2], kb[3]);
            }
        }
        #pragma unroll
        for (int mt = 0; mt < 2; mt++)
            #pragma unroll
            for (int nt = 0; nt < 2; nt++) {
                int lr = wm * 32 + mt * 16 + (lane >> 2);
                int lc = wn * 16 + nt * 8 + (lane & 3) * 2;
                float bf0 = b_proj[lc], bf1 = b_proj[lc + 1];
                yep[lr * 100 + lc]           = acc[mt][nt][0] + bf0;
                yep[lr * 100 + lc + 1]       = acc[mt][nt][1] + bf1;
                yep[(lr + 8) * 100 + lc]     = acc[mt][nt][2] + bf0;
                yep[(lr + 8) * 100 + lc + 1] = acc[mt][nt][3] + bf1;
            }
    }
    __syncthreads();

    // ---- phase 4: residual (x gather) + LN2; y stays in smem, ln2 -> sA ----
    for (int lr = warp; lr < 128; lr += 24) {
        int dt = lr >> 6, dh = (lr >> 3) & 7, dw = lr & 7;
        int t = tb * 2 + dt, h = hb * 8 + dh, w = wb * 8 + dw;
        int ti = (t + 1) & 7, hi = (h + 4) & 127, wi = (w + 4) & 127;
        size_t m = ((size_t)((bi * 8 + ti) * 128 + hi)) * 128 + wi;

        const float* xrow = x + m * 96;
        float v0 = yep[lr * 100 + lane]      + xrow[lane];
        float v1 = yep[lr * 100 + lane + 32] + xrow[lane + 32];
        float v2 = yep[lr * 100 + lane + 64] + xrow[lane + 64];
        yep[lr * 100 + lane]      = v0;
        yep[lr * 100 + lane + 32] = v1;
        yep[lr * 100 + lane + 64] = v2;

        float s  = v0 + v1 + v2;
        float s2 = v0 * v0 + v1 * v1 + v2 * v2;
        #pragma unroll
        for (int o = 16; o; o >>= 1) {
            s  += __shfl_xor_sync(0xffffffffu, s,  o);
            s2 += __shfl_xor_sync(0xffffffffu, s2, o);
        }
        float mean = s * (1.0f / 96.0f);
        float var  = s2 * (1.0f / 96.0f) - mean * mean;
        float rstd = rsqrtf(var + 1e-5f);
        __nv_bfloat16* orow = sA + lr * 104;
        orow[lane]      = __float2bfloat16((v0 - mean) * rstd * g2[lane]      + b2[lane]);
        orow[lane + 32] = __float2bfloat16((v1 - mean) * rstd * g2[lane + 32] + b2[lane + 32]);
        orow[lane + 64] = __float2bfloat16((v2 - mean) * rstd * g2[lane + 64] + b2[lane + 64]);
    }

    // ---- phase 5: MLP (two halves), fc2 acc in registers ----
    const int wm = warp & 3, wn = warp >> 2;     // 4m x 6n
    float acc2[2][2][4] = {};
    const uint32_t aln = s2u(sA + (wm * 32 + (lane & 15)) * 104 + (lane >> 4) * 8);
    const uint32_t ah  = s2u(sHID + (wm * 32 + (lane & 15)) * 200 + (lane >> 4) * 8);
    const uint32_t bw1 = s2u(sW + (wn * 32 + ((lane >> 4) << 3) + (lane & 7)) * 104
                                + ((lane >> 3) & 1) * 8);
    const uint32_t bw2 = s2u(sW + (wn * 16 + ((lane >> 4) << 3) + (lane & 7)) * 200
                                + ((lane >> 3) & 1) * 8);

    #pragma unroll
    for (int hf = 0; hf < 2; hf++) {
        __syncthreads();   // y/ln2 ready (hf=0) or prev fc2 done (hf=1)
        // load W1 half: rows [hf*192, hf*192+192), stride 104
        for (int gi = tid; gi < 2304; gi += 768) {
            int row = gi / 12, q = gi - row * 12;
            *(uint4*)(sW + row * 104 + q * 8) =
                *(const uint4*)(w1 + (size_t)(hf * 192 + row) * 96 + q * 8);
        }
        __syncthreads();

        // fc1 half: (128x96)@(192x96)^T + bias + GELU -> sHID
        {
            float acc[2][4][4] = {};
            #pragma unroll
            for (int ks = 0; ks < 6; ks++) {
                uint32_t a[2][4], bf[2][4];
                #pragma unroll
                for (int mt = 0; mt < 2; mt++)
                    LDSM_X4(a[mt][0], a[mt][1], a[mt][2], a[mt][3],
                            aln + mt * (16 * 104 * 2) + ks * 32);
                #pragma unroll
                for (int ng = 0; ng < 2; ng++)
                    LDSM_X4(bf[ng][0], bf[ng][1], bf[ng][2], bf[ng][3],
                            bw1 + ng * (16 * 104 * 2) + ks * 32);
                #pragma unroll
                for (int mt = 0; mt < 2; mt++)
                    #pragma unroll
                    for (int nt = 0; nt < 4; nt++) {
                        int ng = nt >> 1, pr = (nt & 1) * 2;
                        MMA_BF16(acc[mt][nt], a[mt][0], a[mt][1], a[mt][2], a[mt][3],
                                 bf[ng][pr], bf[ng][pr + 1]);
                    }
            }
            #pragma unroll
            for (int mt = 0; mt < 2; mt++)
                #pragma unroll
                for (int nt = 0; nt < 4; nt++) {
                    int lr  = wm * 32 + mt * 16 + (lane >> 2);
                    int col = wn * 32 + nt * 8 + (lane & 3) * 2;
                    int gcol = hf * 192 + col;
                    float bf0 = bias1[gcol], bf1 = bias1[gcol + 1];
                    float v0 = acc[mt][nt][0] + bf0, v1 = acc[mt][nt][1] + bf1;
                    float v2 = acc[mt][nt][2] + bf0, v3 = acc[mt][nt][3] + bf1;
                    v0 = 0.5f * v0 * (1.0f + erff(v0 * 0.70710678118654752f));
                    v1 = 0.5f * v1 * (1.0f + erff(v1 * 0.70710678118654752f));
                    v2 = 0.5f * v2 * (1.0f + erff(v2 * 0.70710678118654752f));
                    v3 = 0.5f * v3 * (1.0f + erff(v3 * 0.70710678118654752f));
                    __nv_bfloat162 p0, p1;
                    p0.x = __float2bfloat16(v0); p0.y = __float2bfloat16(v1);
                    p1.x = __float2bfloat16(v2); p1.y = __float2bfloat16(v3);
                    *(__nv_bfloat162*)(sHID + lr * 200 + col)       = p0;
                    *(__nv_bfloat162*)(sHID + (lr + 8) * 200 + col) = p1;
                }
        }
        __syncthreads();

        // load W2 half: 96 rows x cols [hf*192, hf*192+192), stride 200
        for (int gi = tid; gi < 2304; gi += 768) {
            int row = gi / 24, q = gi - row * 24;
            *(uint4*)(sW + row * 200 + q * 8) =
                *(const uint4*)(w2 + (size_t)row * 384 + hf * 192 + q * 8);
        }
        __syncthreads();

        // fc2 partial: (128x192)@(96x192)^T accumulate
        #pragma unroll
        for (int ks = 0; ks < 12; ks++) {
            uint32_t a[2][4], kb[4];
            #pragma unroll
            for (int mt = 0; mt < 2; mt++)
                LDSM_X4(a[mt][0], a[mt][1], a[mt][2], a[mt][3],
                        ah + mt * (16 * 200 * 2) + ks * 32);
            LDSM_X4(kb[0], kb[1], kb[2], kb[3], bw2 + ks * 32);
            #pragma unroll
            for (int mt = 0; mt < 2; mt++) {
                MMA_BF16(acc2[mt][0], a[mt][0], a[mt][1], a[mt][2], a[mt][3], kb[0], kb[1]);
                MMA_BF16(acc2[mt][1], a[mt][0], a[mt][1], a[mt][2], a[mt][3], kb[2], kb[3]);
            }
        }
    }

    // ---- phase 6: out = fc2 + bias2 + y, scatter natural order (fp32) ----
    #pragma unroll
    for (int mt = 0; mt < 2; mt++) {
        #pragma unroll
        for (int hh = 0; hh < 2; hh++) {
            int lr = wm * 32 + mt * 16 + (lane >> 2) + hh * 8;
            int dt = lr >> 6, dh = (lr >> 3) & 7, dw = lr & 7;
            int t = tb * 2 + dt, h = hb * 8 + dh, w = wb * 8 + dw;
            int ti = (t + 1) & 7, hi = (h + 4) & 127, wi = (w + 4) & 127;
            size_t m = ((size_t)((bi * 8 + ti) * 128 + hi)) * 128 + wi;
            #pragma unroll
            for (int nt = 0; nt < 2; nt++) {
                int lc = wn * 16 + nt * 8 + (lane & 3) * 2;
                float v0 = acc2[mt][nt][hh * 2 + 0] + bias2[lc]     + yep[lr * 100 + lc];
                float v1 = acc2[mt][nt][hh * 2 + 1] + bias2[lc + 1] + yep[lr * 100 + lc + 1];
                *(float2*)(out + m * 96 + lc) = make_float2(v0, v1);
            }
        }
    }
}

// ---------------- launch ----------------
extern "C" void kernel_launch(void* const* d_in, const int* in_sizes, int n_in,
                              void* d_out, int out_size)
{
    const float* x      = (const float*)d_in[0];
    const float* g1     = (const float*)d_in[2];
    const float* b1     = (const float*)d_in[3];
    const float* w_qkv  = (const float*)d_in[4];
    const float* b_qkv  = (const float*)d_in[5];
    const float* w_proj = (const float*)d_in[6];
    const float* b_proj = (const float*)d_in[7];
    const float* g2     = (const float*)d_in[8];
    const float* b2     = (const float*)d_in[9];
    const float* w_fc1  = (const float*)d_in[10];
    const float* b_fc1  = (const float*)d_in[11];
    const float* w_fc2  = (const float*)d_in[12];
    const float* b_fc2  = (const float*)d_in[13];
    float* out = (float*)d_out;

    __nv_bfloat16 *p_wb;
    cudaGetSymbolAddress((void**)&p_wb, g_wb);

    static bool attr_set = false;
    if (!attr_set) {
        cudaFuncSetAttribute(mono_kernel,
                             cudaFuncAttributeMaxDynamicSharedMemorySize, SMEM_MONO);
        attr_set = true;
    }

    convert_w<<<(110592 + 255) / 256, 256>>>(w_qkv, w_proj, w_fc1, w_fc2, p_wb);

    mono_kernel<<<NWIN, 768, SMEM_MONO>>>(
        x, g1, b1,
        p_wb + WB_QKV, b_qkv, p_wb + WB_PROJ, b_proj,
        g2, b2,
        p_wb + WB_FC1, b_fc1, p_wb + WB_FC2, b_fc2,
        out);
}

// round 10
// speedup vs baseline: 1.0031x; 1.0031x over previous
#include <cuda_runtime.h>
#include <cuda_bf16.h>
#include <math.h>
#include <stdint.h>

// ---------------- problem constants ----------------
#define NTOK (2*8*128*128)          // 262144 tokens
#define NWIN (NTOK/128)             // 2048 windows
#define SCALE 0.25f

// ---------------- scratch ----------------
__device__ __nv_bfloat16 g_wb [110592];              // bf16 weights

#define WB_QKV  0
#define WB_PROJ 27648
#define WB_FC1  36864
#define WB_FC2  73728

static __device__ __forceinline__ uint32_t s2u(const void* p) {
    return (uint32_t)__cvta_generic_to_shared(p);
}

#define LDSM_X4(r0,r1,r2,r3,addr) \
    asm volatile("ldmatrix.sync.aligned.m8n8.x4.shared.b16 {%0,%1,%2,%3}, [%4];" \
        : "=r"(r0),"=r"(r1),"=r"(r2),"=r"(r3) : "r"(addr))

#define LDSM_X4_T(r0,r1,r2,r3,addr) \
    asm volatile("ldmatrix.sync.aligned.m8n8.x4.trans.shared.b16 {%0,%1,%2,%3}, [%4];" \
        : "=r"(r0),"=r"(r1),"=r"(r2),"=r"(r3) : "r"(addr))

#define MMA_BF16(c,a0,a1,a2,a3,b0,b1) \
    asm volatile("mma.sync.aligned.m16n8k16.row.col.f32.bf16.bf16.f32 " \
        "{%0,%1,%2,%3},{%4,%5,%6,%7},{%8,%9},{%0,%1,%2,%3};" \
        : "+f"(c[0]),"+f"(c[1]),"+f"(c[2]),"+f"(c[3]) \
        : "r"(a0),"r"(a1),"r"(a2),"r"(a3),"r"(b0),"r"(b1))

// ---------------- weight conversion fp32 -> bf16 ----------------
__global__ void convert_w(const float* __restrict__ wq, const float* __restrict__ wp,
                          const float* __restrict__ w1, const float* __restrict__ w2,
                          __nv_bfloat16* __restrict__ out)
{
    int i = blockIdx.x * 256 + threadIdx.x;
    if (i < 27648)       out[i] = __float2bfloat16(wq[i]);
    else if (i < 36864)  out[i] = __float2bfloat16(wp[i - 27648]);
    else if (i < 73728)  out[i] = __float2bfloat16(w1[i - 36864]);
    else if (i < 110592) out[i] = __float2bfloat16(w2[i - 73728]);
}

// ================= MONO kernel: entire Swin block, one CTA per window =================
// smem layout (bf16 element offsets):
//   sA   [0,      13312)  128x104  LN1 out / attn out / LN2 out
//   sW   [13312,  43264)  288x104  Wqkv -> Wproj -> W1 halves (192x104) -> W2 halves (96x200)
//   sQKV [43264,  81152)  128x296  qkv; then y as fp32 128x100 (25600 elems)
//   sHID [68864,  94464)  128x200  MLP hidden half (reuses dead qkv tail)
//   lab  [94464,  94720)  128 ints
#define S_A    0
#define S_W    13312
#define S_QKV  43264
#define S_HID  68864
#define S_LAB  94464
#define SMEM_MONO ((S_LAB + 256) * 2)

__global__ __launch_bounds__(768, 1) void mono_kernel(
    const float* __restrict__ x,
    const float* __restrict__ g1, const float* __restrict__ b1,
    const __nv_bfloat16* __restrict__ wqkv, const float* __restrict__ b_qkv,
    const __nv_bfloat16* __restrict__ wproj, const float* __restrict__ b_proj,
    const float* __restrict__ g2, const float* __restrict__ b2,
    const __nv_bfloat16* __restrict__ w1, const float* __restrict__ bias1,
    const __nv_bfloat16* __restrict__ w2, const float* __restrict__ bias2,
    float* __restrict__ out)
{
    extern __shared__ __align__(16) char smem_raw[];
    __nv_bfloat16* sA   = (__nv_bfloat16*)smem_raw;
    __nv_bfloat16* sW   = sA + S_W;
    __nv_bfloat16* sQKV = sA + S_QKV;
    __nv_bfloat16* sHID = sA + S_HID;
    int*   lab = (int*)(sA + S_LAB);
    float* yep = (float*)sQKV;    // proj staging then y (fp32 128x100)

    const int win  = blockIdx.x;
    const int tid  = threadIdx.x;
    const int lane = tid & 31;
    const int warp = tid >> 5;

    const int wr = win & 1023;
    const int tb = wr >> 8, hb = (wr >> 4) & 15, wb = wr & 15;
    const int bi = win >> 10;

    // ---- phase 0: labels + Wqkv load + LN1 (shift gather) ----
    if (tid < 128) {
        int n = tid;
        int lt = (tb == 3) ? (n >> 6) : 0;
        int lh = (hb == 15) ? ((n >> 5) & 1) : 0;
        int lw = (wb == 15) ? ((n >> 2) & 1) : 0;
        lab[n] = lt | (lh << 1) | (lw << 2);
    }
    for (int gi = tid; gi < 3456; gi += 768) {
        int row = gi / 12, q = gi - row * 12;
        *(uint4*)(sW + row * 104 + q * 8) = *(const uint4*)(wqkv + (size_t)row * 96 + q * 8);
    }
    for (int tok = warp; tok < 128; tok += 24) {
        int dt = tok >> 6, dh = (tok >> 3) & 7, dw = tok & 7;
        int t = tb * 2 + dt, h = hb * 8 + dh, w = wb * 8 + dw;
        int ti = (t + 1) & 7, hi = (h + 4) & 127, wi = (w + 4) & 127;
        size_t src = ((size_t)((bi * 8 + ti) * 128 + hi)) * 128 + wi;
        const float* row = x + src * 96;
        float v0 = row[lane], v1 = row[lane + 32], v2 = row[lane + 64];
        float s  = v0 + v1 + v2;
        float s2 = v0 * v0 + v1 * v1 + v2 * v2;
        #pragma unroll
        for (int o = 16; o; o >>= 1) {
            s  += __shfl_xor_sync(0xffffffffu, s,  o);
            s2 += __shfl_xor_sync(0xffffffffu, s2, o);
        }
        float mean = s * (1.0f / 96.0f);
        float var  = s2 * (1.0f / 96.0f) - mean * mean;
        float rstd = rsqrtf(var + 1e-5f);
        __nv_bfloat16* orow = sA + tok * 104;
        orow[lane]      = __float2bfloat16((v0 - mean) * rstd * g1[lane]      + b1[lane]);
        orow[lane + 32] = __float2bfloat16((v1 - mean) * rstd * g1[lane + 32] + b1[lane + 32]);
        orow[lane + 64] = __float2bfloat16((v2 - mean) * rstd * g1[lane + 64] + b1[lane + 64]);
    }
    __syncthreads();

    // ---- phase 1: QKV GEMM -> sQKV (+bias, bf16) ----
    {
        const int wm = warp & 3, wn = warp >> 2;   // 4m x 6n
        float acc[2][6][4] = {};
        const uint32_t a0 = s2u(sA + (wm * 32 + (lane & 15)) * 104 + (lane >> 4) * 8);
        const uint32_t b0 = s2u(sW + (wn * 48 + ((lane >> 4) << 3) + (lane & 7)) * 104
                                   + ((lane >> 3) & 1) * 8);
        #pragma unroll
        for (int ks = 0; ks < 6; ks++) {
            uint32_t a[2][4], bf[3][4];
            #pragma unroll
            for (int mt = 0; mt < 2; mt++)
                LDSM_X4(a[mt][0], a[mt][1], a[mt][2], a[mt][3],
                        a0 + mt * (16 * 104 * 2) + ks * 32);
            #pragma unroll
            for (int ng = 0; ng < 3; ng++)
                LDSM_X4(bf[ng][0], bf[ng][1], bf[ng][2], bf[ng][3],
                        b0 + ng * (16 * 104 * 2) + ks * 32);
            #pragma unroll
            for (int mt = 0; mt < 2; mt++)
                #pragma unroll
                for (int nt = 0; nt < 6; nt++) {
                    int ng = nt >> 1, pr = (nt & 1) * 2;
                    MMA_BF16(acc[mt][nt], a[mt][0], a[mt][1], a[mt][2], a[mt][3],
                             bf[ng][pr], bf[ng][pr + 1]);
                }
        }
        #pragma unroll
        for (int mt = 0; mt < 2; mt++)
            #pragma unroll
            for (int nt = 0; nt < 6; nt++) {
                int row = wm * 32 + mt * 16 + (lane >> 2);
                int col = wn * 48 + nt * 8 + (lane & 3) * 2;
                float bf0 = b_qkv[col], bf1 = b_qkv[col + 1];
                __nv_bfloat162 p0, p1;
                p0.x = __float2bfloat16(acc[mt][nt][0] + bf0);
                p0.y = __float2bfloat16(acc[mt][nt][1] + bf1);
                p1.x = __float2bfloat16(acc[mt][nt][2] + bf0);
                p1.y = __float2bfloat16(acc[mt][nt][3] + bf1);
                *(__nv_bfloat162*)(sQKV + row * 296 + col)       = p0;
                *(__nv_bfloat162*)(sQKV + (row + 8) * 296 + col) = p1;
            }
    }
    __syncthreads();

    // ---- phase 2: attention (6 heads x 4 warps) + Wproj prefetch ----
    for (int gi = tid; gi < 1152; gi += 768) {
        int row = gi / 12, q = gi - row * 12;
        *(uint4*)(sW + row * 104 + q * 8) = *(const uint4*)(wproj + (size_t)row * 96 + q * 8);
    }
    {
        const int head = warp >> 2;
        const int warpRow = (warp & 3) * 32;
        const int hoff = head * 16;
        const bool masked = (tb == 3) || (hb == 15) || (wb == 15);

        #pragma unroll
        for (int mt = 0; mt < 2; mt++) {
            const int rbase = warpRow + mt * 16 + (lane >> 2);
            uint32_t qa[4];
            {
                uint32_t qaddr = s2u(sQKV + (warpRow + mt * 16 + (lane & 15)) * 296
                                          + hoff + (lane >> 4) * 8);
                LDSM_X4(qa[0], qa[1], qa[2], qa[3], qaddr);
            }
            const int lr0 = lab[rbase];
            const int lr1 = lab[rbase + 8];

            float sum0 = 0.0f, sum1 = 0.0f;
            uint32_t p[16][2];

            const uint32_t kaddr0 = s2u(sQKV + (((lane >> 4) << 3) + (lane & 7)) * 296
                                             + 96 + hoff + ((lane >> 3) & 1) * 8);
            #pragma unroll
            for (int j2 = 0; j2 < 8; j2++) {
                uint32_t kb[4];
                LDSM_X4(kb[0], kb[1], kb[2], kb[3], kaddr0 + j2 * (16 * 296 * 2));
                float c0[4] = {}, c1[4] = {};
                MMA_BF16(c0, qa[0], qa[1], qa[2], qa[3], kb[0], kb[1]);
                MMA_BF16(c1, qa[0], qa[1], qa[2], qa[3], kb[2], kb[3]);
                #pragma unroll
                for (int half = 0; half < 2; half++) {
                    float* c = half ? c1 : c0;
                    int j = 2 * j2 + half;
                    int col0 = j * 8 + (lane & 3) * 2;
                    float e00 = __expf(SCALE * c[0]);
                    float e01 = __expf(SCALE * c[1]);
                    float e10 = __expf(SCALE * c[2]);
                    float e11 = __expf(SCALE * c[3]);
                    if (masked) {
                        int lc0 = lab[col0], lc1 = lab[col0 + 1];
                        e00 = (lc0 == lr0) ? e00 : 0.0f;
                        e01 = (lc1 == lr0) ? e01 : 0.0f;
                        e10 = (lc0 == lr1) ? e10 : 0.0f;
                        e11 = (lc1 == lr1) ? e11 : 0.0f;
                    }
                    __nv_bfloat162 lo = __floats2bfloat162_rn(e00, e01);
                    __nv_bfloat162 hi = __floats2bfloat162_rn(e10, e11);
                    sum0 += __low2float(lo) + __high2float(lo);
                    sum1 += __low2float(hi) + __high2float(hi);
                    p[j][0] = *(uint32_t*)&lo;
                    p[j][1] = *(uint32_t*)&hi;
                }
            }
            sum0 += __shfl_xor_sync(0xffffffffu, sum0, 1);
            sum0 += __shfl_xor_sync(0xffffffffu, sum0, 2);
            sum1 += __shfl_xor_sync(0xffffffffu, sum1, 1);
            sum1 += __shfl_xor_sync(0xffffffffu, sum1, 2);
            float inv0 = 1.0f / sum0;
            float inv1 = 1.0f / sum1;

            float o[2][4] = {};
            const uint32_t vaddr0 = s2u(sQKV + (lane & 15) * 296 + 192 + hoff + (lane >> 4) * 8);
            #pragma unroll
            for (int kc = 0; kc < 8; kc++) {
                uint32_t vb[4];
                LDSM_X4_T(vb[0], vb[1], vb[2], vb[3], vaddr0 + kc * (16 * 296 * 2));
                MMA_BF16(o[0], p[2*kc][0], p[2*kc][1], p[2*kc+1][0], p[2*kc+1][1], vb[0], vb[1]);
                MMA_BF16(o[1], p[2*kc][0], p[2*kc][1], p[2*kc+1][0], p[2*kc+1][1], vb[2], vb[3]);
            }
            #pragma unroll
            for (int nt = 0; nt < 2; nt++) {
                int col = hoff + nt * 8 + (lane & 3) * 2;
                __nv_bfloat162 w0 = __floats2bfloat162_rn(o[nt][0] * inv0, o[nt][1] * inv0);
                __nv_bfloat162 w1 = __floats2bfloat162_rn(o[nt][2] * inv1, o[nt][3] * inv1);
                *(__nv_bfloat162*)(sA + rbase * 104 + col)       = w0;
                *(__nv_bfloat162*)(sA + (rbase + 8) * 104 + col) = w1;
            }
        }
    }
    __syncthreads();

    // ---- phase 3: proj GEMM -> yep staging (fp32 +bias) ----
    {
        const int wm = warp & 3, wn = warp >> 2;
        float acc[2][2][4] = {};
        const uint32_t a0 = s2u(sA + (wm * 32 + (lane & 15)) * 104 + (lane >> 4) * 8);
        const uint32_t b0 = s2u(sW + (wn * 16 + ((lane >> 4) << 3) + (lane & 7)) * 104
                                   + ((lane >> 3) & 1) * 8);
        #pragma unroll
        for (int ks = 0; ks < 6; ks++) {
            uint32_t a[2][4], kb[4];
            #pragma unroll
            for (int mt = 0; mt < 2; mt++)
                LDSM_X4(a[mt][0], a[mt][1], a[mt][2], a[mt][3],
                        a0 + mt * (16 * 104 * 2) + ks * 32);
            LDSM_X4(kb[0], kb[1], kb[2], kb[3], b0 + ks * 32);
            #pragma unroll
            for (int mt = 0; mt < 2; mt++) {
                MMA_BF16(acc[mt][0], a[mt][0], a[mt][1], a[mt][2], a[mt][3], kb[0], kb[1]);
                MMA_BF16(acc[mt][1], a[mt][0], a[mt][1], a[mt][2], a[mt][3], kb[2], kb[3]);
            }
        }
        #pragma unroll
        for (int mt = 0; mt < 2; mt++)
            #pragma unroll
            for (int nt = 0; nt < 2; nt++) {
                int lr = wm * 32 + mt * 16 + (lane >> 2);
                int lc = wn * 16 + nt * 8 + (lane & 3) * 2;
                float bf0 = b_proj[lc], bf1 = b_proj[lc + 1];
                yep[lr * 100 + lc]           = acc[mt][nt][0] + bf0;
                yep[lr * 100 + lc + 1]       = acc[mt][nt][1] + bf1;
                yep[(lr + 8) * 100 + lc]     = acc[mt][nt][2] + bf0;
                yep[(lr + 8) * 100 + lc + 1] = acc[mt][nt][3] + bf1;
            }
    }
    __syncthreads();

    // ---- phase 4: residual (x gather) + LN2; y stays in smem, ln2 -> sA ----
    for (int lr = warp; lr < 128; lr += 24) {
        int dt = lr >> 6, dh = (lr >> 3) & 7, dw = lr & 7;
        int t = tb * 2 + dt, h = hb * 8 + dh, w = wb * 8 + dw;
        int ti = (t + 1) & 7, hi = (h + 4) & 127, wi = (w + 4) & 127;
        size_t m = ((size_t)((bi * 8 + ti) * 128 + hi)) * 128 + wi;

        const float* xrow = x + m * 96;
        float v0 = yep[lr * 100 + lane]      + xrow[lane];
        float v1 = yep[lr * 100 + lane + 32] + xrow[lane + 32];
        float v2 = yep[lr * 100 + lane + 64] + xrow[lane + 64];
        yep[lr * 100 + lane]      = v0;
        yep[lr * 100 + lane + 32] = v1;
        yep[lr * 100 + lane + 64] = v2;

        float s  = v0 + v1 + v2;
        float s2 = v0 * v0 + v1 * v1 + v2 * v2;
        #pragma unroll
        for (int o = 16; o; o >>= 1) {
            s  += __shfl_xor_sync(0xffffffffu, s,  o);
            s2 += __shfl_xor_sync(0xffffffffu, s2, o);
        }
        float mean = s * (1.0f / 96.0f);
        float var  = s2 * (1.0f / 96.0f) - mean * mean;
        float rstd = rsqrtf(var + 1e-5f);
        __nv_bfloat16* orow = sA + lr * 104;
        orow[lane]      = __float2bfloat16((v0 - mean) * rstd * g2[lane]      + b2[lane]);
        orow[lane + 32] = __float2bfloat16((v1 - mean) * rstd * g2[lane + 32] + b2[lane + 32]);
        orow[lane + 64] = __float2bfloat16((v2 - mean) * rstd * g2[lane + 64] + b2[lane + 64]);
    }

    // ---- phase 5: MLP (two halves), fc2 acc in registers ----
    const int wm = warp & 3, wn = warp >> 2;     // 4m x 6n
    float acc2[2][2][4] = {};
    const uint32_t aln = s2u(sA + (wm * 32 + (lane & 15)) * 104 + (lane >> 4) * 8);
    const uint32_t ah  = s2u(sHID + (wm * 32 + (lane & 15)) * 200 + (lane >> 4) * 8);
    const uint32_t bw1 = s2u(sW + (wn * 32 + ((lane >> 4) << 3) + (lane & 7)) * 104
                                + ((lane >> 3) & 1) * 8);
    const uint32_t bw2 = s2u(sW + (wn * 16 + ((lane >> 4) << 3) + (lane & 7)) * 200
                                + ((lane >> 3) & 1) * 8);

    #pragma unroll
    for (int hf = 0; hf < 2; hf++) {
        __syncthreads();   // y/ln2 ready (hf=0) or prev fc2 done (hf=1)
        // load W1 half: rows [hf*192, hf*192+192), stride 104
        for (int gi = tid; gi < 2304; gi += 768) {
            int row = gi / 12, q = gi - row * 12;
            *(uint4*)(sW + row * 104 + q * 8) =
                *(const uint4*)(w1 + (size_t)(hf * 192 + row) * 96 + q * 8);
        }
        __syncthreads();

        // fc1 half: (128x96)@(192x96)^T + bias + GELU -> sHID
        {
            float acc[2][4][4] = {};
            #pragma unroll
            for (int ks = 0; ks < 6; ks++) {
                uint32_t a[2][4], bf[2][4];
                #pragma unroll
                for (int mt = 0; mt < 2; mt++)
                    LDSM_X4(a[mt][0], a[mt][1], a[mt][2], a[mt][3],
                            aln + mt * (16 * 104 * 2) + ks * 32);
                #pragma unroll
                for (int ng = 0; ng < 2; ng++)
                    LDSM_X4(bf[ng][0], bf[ng][1], bf[ng][2], bf[ng][3],
                            bw1 + ng * (16 * 104 * 2) + ks * 32);
                #pragma unroll
                for (int mt = 0; mt < 2; mt++)
                    #pragma unroll
                    for (int nt = 0; nt < 4; nt++) {
                        int ng = nt >> 1, pr = (nt & 1) * 2;
                        MMA_BF16(acc[mt][nt], a[mt][0], a[mt][1], a[mt][2], a[mt][3],
                                 bf[ng][pr], bf[ng][pr + 1]);
                    }
            }
            #pragma unroll
            for (int mt = 0; mt < 2; mt++)
                #pragma unroll
                for (int nt = 0; nt < 4; nt++) {
                    int lr  = wm * 32 + mt * 16 + (lane >> 2);
                    int col = wn * 32 + nt * 8 + (lane & 3) * 2;
                    int gcol = hf * 192 + col;
                    float bf0 = bias1[gcol], bf1 = bias1[gcol + 1];
                    float v0 = acc[mt][nt][0] + bf0, v1 = acc[mt][nt][1] + bf1;
                    float v2 = acc[mt][nt][2] + bf0, v3 = acc[mt][nt][3] + bf1;
                    v0 = 0.5f * v0 * (1.0f + erff(v0 * 0.70710678118654752f));
                    v1 = 0.5f * v1 * (1.0f + erff(v1 * 0.70710678118654752f));
                    v2 = 0.5f * v2 * (1.0f + erff(v2 * 0.70710678118654752f));
                    v3 = 0.5f * v3 * (1.0f + erff(v3 * 0.70710678118654752f));
                    __nv_bfloat162 p0, p1;
                    p0.x = __float2bfloat16(v0); p0.y = __float2bfloat16(v1);
                    p1.x = __float2bfloat16(v2); p1.y = __float2bfloat16(v3);
                    *(__nv_bfloat162*)(sHID + lr * 200 + col)       = p0;
                    *(__nv_bfloat162*)(sHID + (lr + 8) * 200 + col) = p1;
                }
        }
        __syncthreads();

        // load W2 half: 96 rows x cols [hf*192, hf*192+192), stride 200
        for (int gi = tid; gi < 2304; gi += 768) {
            int row = gi / 24, q = gi - row * 24;
            *(uint4*)(sW + row * 200 + q * 8) =
                *(const uint4*)(w2 + (size_t)row * 384 + hf * 192 + q * 8);
        }
        __syncthreads();

        // fc2 partial: (128x192)@(96x192)^T accumulate
        #pragma unroll
        for (int ks = 0; ks < 12; ks++) {
            uint32_t a[2][4], kb[4];
            #pragma unroll
            for (int mt = 0; mt < 2; mt++)
                LDSM_X4(a[mt][0], a[mt][1], a[mt][2], a[mt][3],
                        ah + mt * (16 * 200 * 2) + ks * 32);
            LDSM_X4(kb[0], kb[1], kb[2], kb[3], bw2 + ks * 32);
            #pragma unroll
            for (int mt = 0; mt < 2; mt++) {
                MMA_BF16(acc2[mt][0], a[mt][0], a[mt][1], a[mt][2], a[mt][3], kb[0], kb[1]);
                MMA_BF16(acc2[mt][1], a[mt][0], a[mt][1], a[mt][2], a[mt][3], kb[2], kb[3]);
            }
        }
    }

    // ---- phase 6: out = fc2 + bias2 + y, scatter natural order (fp32) ----
    #pragma unroll
    for (int mt = 0; mt < 2; mt++) {
        #pragma unroll
        for (int hh = 0; hh < 2; hh++) {
            int lr = wm * 32 + mt * 16 + (lane >> 2) + hh * 8;
            int dt = lr >> 6, dh = (lr >> 3) & 7, dw = lr & 7;
            int t = tb * 2 + dt, h = hb * 8 + dh, w = wb * 8 + dw;
            int ti = (t + 1) & 7, hi = (h + 4) & 127, wi = (w + 4) & 127;
            size_t m = ((size_t)((bi * 8 + ti) * 128 + hi)) * 128 + wi;
            #pragma unroll
            for (int nt = 0; nt < 2; nt++) {
                int lc = wn * 16 + nt * 8 + (lane & 3) * 2;
                float v0 = acc2[mt][nt][hh * 2 + 0] + bias2[lc]     + yep[lr * 100 + lc];
                float v1 = acc2[mt][nt][hh * 2 + 1] + bias2[lc + 1] + yep[lr * 100 + lc + 1];
                *(float2*)(out + m * 96 + lc) = make_float2(v0, v1);
            }
        }
    }
}

// ---------------- launch ----------------
extern "C" void kernel_launch(void* const* d_in, const int* in_sizes, int n_in,
                              void* d_out, int out_size)
{
    const float* x      = (const float*)d_in[0];
    const float* g1     = (const float*)d_in[2];
    const float* b1     = (const float*)d_in[3];
    const float* w_qkv  = (const float*)d_in[4];
    const float* b_qkv  = (const float*)d_in[5];
    const float* w_proj = (const float*)d_in[6];
    const float* b_proj = (const float*)d_in[7];
    const float* g2     = (const float*)d_in[8];
    const float* b2     = (const float*)d_in[9];
    const float* w_fc1  = (const float*)d_in[10];
    const float* b_fc1  = (const float*)d_in[11];
    const float* w_fc2  = (const float*)d_in[12];
    const float* b_fc2  = (const float*)d_in[13];
    float* out = (float*)d_out;

    __nv_bfloat16 *p_wb;
    cudaGetSymbolAddress((void**)&p_wb, g_wb);

    static bool attr_set = false;
    if (!attr_set) {
        cudaFuncSetAttribute(mono_kernel,
                             cudaFuncAttributeMaxDynamicSharedMemorySize, SMEM_MONO);
        attr_set = true;
    }

    convert_w<<<(110592 + 255) / 256, 256>>>(w_qkv, w_proj, w_fc1, w_fc2, p_wb);

    mono_kernel<<<NWIN, 768, SMEM_MONO>>>(
        x, g1, b1,
        p_wb + WB_QKV, b_qkv, p_wb + WB_PROJ, b_proj,
        g2, b2,
        p_wb + WB_FC1, b_fc1, p_wb + WB_FC2, b_fc2,
        out);
}

// round 11
// speedup vs baseline: 1.0377x; 1.0345x over previous
#include <cuda_runtime.h>
#include <cuda_bf16.h>
#include <math.h>
#include <stdint.h>

// ---------------- problem constants ----------------
#define NTOK (2*8*128*128)          // 262144 tokens
#define NWIN (NTOK/128)             // 2048 windows
#define SCALE 0.25f

// ---------------- scratch ----------------
__device__ __nv_bfloat16 g_wb [110592];              // bf16 weights

#define WB_QKV  0
#define WB_PROJ 27648
#define WB_FC1  36864
#define WB_FC2  73728

static __device__ __forceinline__ uint32_t s2u(const void* p) {
    return (uint32_t)__cvta_generic_to_shared(p);
}

#define LDSM_X4(r0,r1,r2,r3,addr) \
    asm volatile("ldmatrix.sync.aligned.m8n8.x4.shared.b16 {%0,%1,%2,%3}, [%4];" \
        : "=r"(r0),"=r"(r1),"=r"(r2),"=r"(r3) : "r"(addr))

#define LDSM_X2(r0,r1,addr) \
    asm volatile("ldmatrix.sync.aligned.m8n8.x2.shared.b16 {%0,%1}, [%2];" \
        : "=r"(r0),"=r"(r1) : "r"(addr))

#define LDSM_X4_T(r0,r1,r2,r3,addr) \
    asm volatile("ldmatrix.sync.aligned.m8n8.x4.trans.shared.b16 {%0,%1,%2,%3}, [%4];" \
        : "=r"(r0),"=r"(r1),"=r"(r2),"=r"(r3) : "r"(addr))

#define MMA_BF16(c,a0,a1,a2,a3,b0,b1) \
    asm volatile("mma.sync.aligned.m16n8k16.row.col.f32.bf16.bf16.f32 " \
        "{%0,%1,%2,%3},{%4,%5,%6,%7},{%8,%9},{%0,%1,%2,%3};" \
        : "+f"(c[0]),"+f"(c[1]),"+f"(c[2]),"+f"(c[3]) \
        : "r"(a0),"r"(a1),"r"(a2),"r"(a3),"r"(b0),"r"(b1))

// ---------------- weight conversion fp32 -> bf16 ----------------
__global__ void convert_w(const float* __restrict__ wq, const float* __restrict__ wp,
                          const float* __restrict__ w1, const float* __restrict__ w2,
                          __nv_bfloat16* __restrict__ out)
{
    int i = blockIdx.x * 256 + threadIdx.x;
    if (i < 27648)       out[i] = __float2bfloat16(wq[i]);
    else if (i < 36864)  out[i] = __float2bfloat16(wp[i - 27648]);
    else if (i < 73728)  out[i] = __float2bfloat16(w1[i - 36864]);
    else if (i < 110592) out[i] = __float2bfloat16(w2[i - 73728]);
}

// ================= MONO kernel, 512 threads, 2 CTAs/SM =================
// smem (bf16 elems):
//   sQKV [0, 37888)      128x296: q-slots cols 0..95 (LN1 -> q -> attn-out -> hidden),
//                        kv-slots cols 96..287 (k,v -> y fp32 stride-148 @ float col 48)
//   pW   [37888, 56576)  18688: weight chunk buffer [0..5376) + LN2 @ +5376 (128x104)
//   lab  @ elem 56576    128 ints
// total = 113664 bytes -> 2 CTAs/SM
#define STRQ 296
#define OFF_W   37888
#define OFF_LN2 (37888 + 5376)
#define OFF_LAB 56576
#define SMEM_MONO 113664

__global__ __launch_bounds__(512, 2) void mono_kernel(
    const float* __restrict__ x,
    const float* __restrict__ g1, const float* __restrict__ b1,
    const __nv_bfloat16* __restrict__ wqkv, const float* __restrict__ b_qkv,
    const __nv_bfloat16* __restrict__ wproj, const float* __restrict__ b_proj,
    const float* __restrict__ g2, const float* __restrict__ b2,
    const __nv_bfloat16* __restrict__ w1, const float* __restrict__ bias1,
    const __nv_bfloat16* __restrict__ w2, const float* __restrict__ bias2,
    float* __restrict__ out)
{
    extern __shared__ __align__(16) char smem_raw[];
    __nv_bfloat16* sQKV = (__nv_bfloat16*)smem_raw;
    __nv_bfloat16* pW   = sQKV + OFF_W;
    __nv_bfloat16* pLN2 = sQKV + OFF_LN2;
    int* lab = (int*)(sQKV + OFF_LAB);
    float* yf = (float*)smem_raw;    // y: yf[row*148 + 48 + col], col 0..95

    const int tid  = threadIdx.x;
    const int lane = tid & 31;
    const int warp = tid >> 5;        // 16 warps
    const int wm = warp & 7, wn = warp >> 3;   // 8m x 2n

    const int win = blockIdx.x;
    const int wr = win & 1023;
    const int tb = wr >> 8, hb = (wr >> 4) & 15, wb = wr & 15;
    const int bi = win >> 10;

    // ---- phase 0: labels + LN1 (shift gather) -> q-slots ----
    if (tid < 128) {
        int n = tid;
        int lt = (tb == 3) ? (n >> 6) : 0;
        int lh = (hb == 15) ? ((n >> 5) & 1) : 0;
        int lw = (wb == 15) ? ((n >> 2) & 1) : 0;
        lab[n] = lt | (lh << 1) | (lw << 2);
    }
    for (int tok = warp; tok < 128; tok += 16) {
        int dt = tok >> 6, dh = (tok >> 3) & 7, dw = tok & 7;
        int t = tb * 2 + dt, h = hb * 8 + dh, w = wb * 8 + dw;
        int ti = (t + 1) & 7, hi = (h + 4) & 127, wi = (w + 4) & 127;
        size_t src = ((size_t)((bi * 8 + ti) * 128 + hi)) * 128 + wi;
        const float* row = x + src * 96;
        float v0 = row[lane], v1 = row[lane + 32], v2 = row[lane + 64];
        float s  = v0 + v1 + v2;
        float s2 = v0 * v0 + v1 * v1 + v2 * v2;
        #pragma unroll
        for (int o = 16; o; o >>= 1) {
            s  += __shfl_xor_sync(0xffffffffu, s,  o);
            s2 += __shfl_xor_sync(0xffffffffu, s2, o);
        }
        float mean = s * (1.0f / 96.0f);
        float var  = s2 * (1.0f / 96.0f) - mean * mean;
        float rstd = rsqrtf(var + 1e-5f);
        __nv_bfloat16* orow = sQKV + tok * STRQ;
        orow[lane]      = __float2bfloat16((v0 - mean) * rstd * g1[lane]      + b1[lane]);
        orow[lane + 32] = __float2bfloat16((v1 - mean) * rstd * g1[lane + 32] + b1[lane + 32]);
        orow[lane + 64] = __float2bfloat16((v2 - mean) * rstd * g1[lane + 64] + b1[lane + 64]);
    }

    // ---- phase 1: QKV GEMM in 3 chunks (k, v, then q last) ----
    const uint32_t aq   = s2u(sQKV + (wm * 16 + (lane & 15)) * STRQ + (lane >> 4) * 8);
    const uint32_t bw48 = s2u(pW + (wn * 48 + ((lane >> 4) << 3) + (lane & 7)) * 104
                                 + ((lane >> 3) & 1) * 8);
    {
        const int ccs[3] = {1, 2, 0};
        #pragma unroll
        for (int ci = 0; ci < 3; ci++) {
            int cc = ccs[ci];
            __syncthreads();
            for (int gi = tid; gi < 1152; gi += 512) {
                int row = gi / 12, q = gi - row * 12;
                *(uint4*)(pW + row * 104 + q * 8) =
                    *(const uint4*)(wqkv + (size_t)(cc * 96 + row) * 96 + q * 8);
            }
            __syncthreads();
            float acc[6][4] = {};
            #pragma unroll
            for (int ks = 0; ks < 6; ks++) {
                uint32_t a[4], bf[3][4];
                LDSM_X4(a[0], a[1], a[2], a[3], aq + ks * 32);
                #pragma unroll
                for (int ng = 0; ng < 3; ng++)
                    LDSM_X4(bf[ng][0], bf[ng][1], bf[ng][2], bf[ng][3],
                            bw48 + ng * (16 * 104 * 2) + ks * 32);
                #pragma unroll
                for (int nt = 0; nt < 6; nt++) {
                    int ng = nt >> 1, pr = (nt & 1) * 2;
                    MMA_BF16(acc[nt], a[0], a[1], a[2], a[3], bf[ng][pr], bf[ng][pr + 1]);
                }
            }
            if (cc == 0) __syncthreads();   // all warps done reading LN1 (q-slots)
            #pragma unroll
            for (int nt = 0; nt < 6; nt++) {
                int lr  = wm * 16 + (lane >> 2);
                int lc  = wn * 48 + nt * 8 + (lane & 3) * 2;
                int gcol = cc * 96 + lc;
                float bf0 = b_qkv[gcol], bf1 = b_qkv[gcol + 1];
                __nv_bfloat162 p0, p1;
                p0.x = __float2bfloat16(acc[nt][0] + bf0);
                p0.y = __float2bfloat16(acc[nt][1] + bf1);
                p1.x = __float2bfloat16(acc[nt][2] + bf0);
                p1.y = __float2bfloat16(acc[nt][3] + bf1);
                *(__nv_bfloat162*)(sQKV + lr * STRQ + gcol)       = p0;
                *(__nv_bfloat162*)(sQKV + (lr + 8) * STRQ + gcol) = p1;
            }
        }
    }
    __syncthreads();

    // ---- phase 2: attention (48 units = 6 heads x 8 row-tiles) + Wproj prefetch ----
    for (int gi = tid; gi < 1152; gi += 512) {
        int row = gi / 12, q = gi - row * 12;
        *(uint4*)(pW + row * 104 + q * 8) = *(const uint4*)(wproj + (size_t)row * 96 + q * 8);
    }
    {
        const bool masked = (tb == 3) || (hb == 15) || (wb == 15);
        for (int u = warp; u < 48; u += 16) {
            int head = u >> 3, rtile = u & 7;
            int hoff = head * 16, r0 = rtile * 16;
            uint32_t qa[4];
            LDSM_X4(qa[0], qa[1], qa[2], qa[3],
                    s2u(sQKV + (r0 + (lane & 15)) * STRQ + hoff + (lane >> 4) * 8));
            const int lr0 = lab[r0 + (lane >> 2)];
            const int lr1 = lab[r0 + 8 + (lane >> 2)];
            const uint32_t kaddr = s2u(sQKV + (((lane >> 4) << 3) + (lane & 7)) * STRQ
                                            + 96 + hoff + ((lane >> 3) & 1) * 8);
            const uint32_t vaddr = s2u(sQKV + (lane & 15) * STRQ + 192 + hoff + (lane >> 4) * 8);
            float o0[4] = {}, o1[4] = {};
            float sum0 = 0.0f, sum1 = 0.0f;
            #pragma unroll
            for (int jg = 0; jg < 8; jg++) {
                uint32_t kb[4];
                LDSM_X4(kb[0], kb[1], kb[2], kb[3], kaddr + jg * (16 * STRQ * 2));
                float c0[4] = {}, c1[4] = {};
                MMA_BF16(c0, qa[0], qa[1], qa[2], qa[3], kb[0], kb[1]);
                MMA_BF16(c1, qa[0], qa[1], qa[2], qa[3], kb[2], kb[3]);
                int colA = jg * 16 + (lane & 3) * 2;
                int colB = colA + 8;
                float e00 = __expf(SCALE * c0[0]);
                float e01 = __expf(SCALE * c0[1]);
                float e10 = __expf(SCALE * c0[2]);
                float e11 = __expf(SCALE * c0[3]);
                float f00 = __expf(SCALE * c1[0]);
                float f01 = __expf(SCALE * c1[1]);
                float f10 = __expf(SCALE * c1[2]);
                float f11 = __expf(SCALE * c1[3]);
                if (masked) {
                    int la0 = lab[colA], la1 = lab[colA + 1];
                    int lb0 = lab[colB], lb1 = lab[colB + 1];
                    e00 = (la0 == lr0) ? e00 : 0.0f;
                    e01 = (la1 == lr0) ? e01 : 0.0f;
                    e10 = (la0 == lr1) ? e10 : 0.0f;
                    e11 = (la1 == lr1) ? e11 : 0.0f;
                    f00 = (lb0 == lr0) ? f00 : 0.0f;
                    f01 = (lb1 == lr0) ? f01 : 0.0f;
                    f10 = (lb0 == lr1) ? f10 : 0.0f;
                    f11 = (lb1 == lr1) ? f11 : 0.0f;
                }
                __nv_bfloat162 a0 = __floats2bfloat162_rn(e00, e01);
                __nv_bfloat162 a1 = __floats2bfloat162_rn(e10, e11);
                __nv_bfloat162 a2 = __floats2bfloat162_rn(f00, f01);
                __nv_bfloat162 a3 = __floats2bfloat162_rn(f10, f11);
                sum0 += __low2float(a0) + __high2float(a0) + __low2float(a2) + __high2float(a2);
                sum1 += __low2float(a1) + __high2float(a1) + __low2float(a3) + __high2float(a3);
                uint32_t vb[4];
                LDSM_X4_T(vb[0], vb[1], vb[2], vb[3], vaddr + jg * (16 * STRQ * 2));
                MMA_BF16(o0, *(uint32_t*)&a0, *(uint32_t*)&a1, *(uint32_t*)&a2, *(uint32_t*)&a3,
                         vb[0], vb[1]);
                MMA_BF16(o1, *(uint32_t*)&a0, *(uint32_t*)&a1, *(uint32_t*)&a2, *(uint32_t*)&a3,
                         vb[2], vb[3]);
            }
            sum0 += __shfl_xor_sync(0xffffffffu, sum0, 1);
            sum0 += __shfl_xor_sync(0xffffffffu, sum0, 2);
            sum1 += __shfl_xor_sync(0xffffffffu, sum1, 1);
            sum1 += __shfl_xor_sync(0xffffffffu, sum1, 2);
            float inv0 = 1.0f / sum0;
            float inv1 = 1.0f / sum1;
            // write attn-out into q-slots (own rows/head only)
            int r = r0 + (lane >> 2);
            #pragma unroll
            for (int nt = 0; nt < 2; nt++) {
                int col = hoff + nt * 8 + (lane & 3) * 2;
                float* o = nt ? o1 : o0;
                __nv_bfloat162 w0 = __floats2bfloat162_rn(o[0] * inv0, o[1] * inv0);
                __nv_bfloat162 w1 = __floats2bfloat162_rn(o[2] * inv1, o[3] * inv1);
                *(__nv_bfloat162*)(sQKV + r * STRQ + col)       = w0;
                *(__nv_bfloat162*)(sQKV + (r + 8) * STRQ + col) = w1;
            }
        }
    }
    __syncthreads();

    // ---- phase 3: proj GEMM (A = attn-out q-slots, B = Wproj) -> y (kv-slots fp32) ----
    {
        float acc[6][4] = {};
        #pragma unroll
        for (int ks = 0; ks < 6; ks++) {
            uint32_t a[4], bf[3][4];
            LDSM_X4(a[0], a[1], a[2], a[3], aq + ks * 32);
            #pragma unroll
            for (int ng = 0; ng < 3; ng++)
                LDSM_X4(bf[ng][0], bf[ng][1], bf[ng][2], bf[ng][3],
                        bw48 + ng * (16 * 104 * 2) + ks * 32);
            #pragma unroll
            for (int nt = 0; nt < 6; nt++) {
                int ng = nt >> 1, pr = (nt & 1) * 2;
                MMA_BF16(acc[nt], a[0], a[1], a[2], a[3], bf[ng][pr], bf[ng][pr + 1]);
            }
        }
        #pragma unroll
        for (int nt = 0; nt < 6; nt++) {
            int lr = wm * 16 + (lane >> 2);
            int lc = wn * 48 + nt * 8 + (lane & 3) * 2;
            float bf0 = b_proj[lc], bf1 = b_proj[lc + 1];
            yf[lr * 148 + 48 + lc]           = acc[nt][0] + bf0;
            yf[lr * 148 + 48 + lc + 1]       = acc[nt][1] + bf1;
            yf[(lr + 8) * 148 + 48 + lc]     = acc[nt][2] + bf0;
            yf[(lr + 8) * 148 + 48 + lc + 1] = acc[nt][3] + bf1;
        }
    }
    __syncthreads();

    // ---- phase 4: y += x (gather); LN2 -> pLN2 ----
    for (int tok = warp; tok < 128; tok += 16) {
        int dt = tok >> 6, dh = (tok >> 3) & 7, dw = tok & 7;
        int t = tb * 2 + dt, h = hb * 8 + dh, w = wb * 8 + dw;
        int ti = (t + 1) & 7, hi = (h + 4) & 127, wi = (w + 4) & 127;
        size_t m = ((size_t)((bi * 8 + ti) * 128 + hi)) * 128 + wi;
        const float* xrow = x + m * 96;
        float* yrow = yf + tok * 148 + 48;
        float v0 = yrow[lane]      + xrow[lane];
        float v1 = yrow[lane + 32] + xrow[lane + 32];
        float v2 = yrow[lane + 64] + xrow[lane + 64];
        yrow[lane]      = v0;
        yrow[lane + 32] = v1;
        yrow[lane + 64] = v2;
        float s  = v0 + v1 + v2;
        float s2 = v0 * v0 + v1 * v1 + v2 * v2;
        #pragma unroll
        for (int o = 16; o; o >>= 1) {
            s  += __shfl_xor_sync(0xffffffffu, s,  o);
            s2 += __shfl_xor_sync(0xffffffffu, s2, o);
        }
        float mean = s * (1.0f / 96.0f);
        float var  = s2 * (1.0f / 96.0f) - mean * mean;
        float rstd = rsqrtf(var + 1e-5f);
        __nv_bfloat16* orow = pLN2 + tok * 104;
        orow[lane]      = __float2bfloat16((v0 - mean) * rstd * g2[lane]      + b2[lane]);
        orow[lane + 32] = __float2bfloat16((v1 - mean) * rstd * g2[lane + 32] + b2[lane + 32]);
        orow[lane + 64] = __float2bfloat16((v2 - mean) * rstd * g2[lane + 64] + b2[lane + 64]);
    }

    // ---- phase 5: MLP in 8 K-chunks of 48; fc2 acc in registers ----
    float acc2[6][4] = {};
    const uint32_t aln = s2u(pLN2 + (wm * 16 + (lane & 15)) * 104 + (lane >> 4) * 8);
    const uint32_t ah  = s2u(sQKV + (wm * 16 + (lane & 15)) * STRQ + (lane >> 4) * 8);
    const uint32_t b1x4 = s2u(pW + (wn * 24 + ((lane >> 4) << 3) + (lane & 7)) * 104
                                 + ((lane >> 3) & 1) * 8);
    const uint32_t b1x2 = s2u(pW + (wn * 24 + 16 + (lane & 7)) * 104 + ((lane >> 3) & 1) * 8);
    const uint32_t b2a  = s2u(pW + (wn * 48 + ((lane >> 4) << 3) + (lane & 7)) * 56
                                 + ((lane >> 3) & 1) * 8);

    for (int c = 0; c < 8; c++) {
        __syncthreads();
        // load W1 chunk: 48 rows x 96
        for (int gi = tid; gi < 576; gi += 512) {
            int row = gi / 12, q = gi - row * 12;
            *(uint4*)(pW + row * 104 + q * 8) =
                *(const uint4*)(w1 + (size_t)(c * 48 + row) * 96 + q * 8);
        }
        __syncthreads();
        // fc1 chunk: (128x96)@(48x96)^T + bias + GELU -> hidden (q-slots cols 0..47)
        {
            float a1[3][4] = {};
            #pragma unroll
            for (int ks = 0; ks < 6; ks++) {
                uint32_t a[4], bx[4], by[2];
                LDSM_X4(a[0], a[1], a[2], a[3], aln + ks * 32);
                LDSM_X4(bx[0], bx[1], bx[2], bx[3], b1x4 + ks * 32);
                LDSM_X2(by[0], by[1], b1x2 + ks * 32);
                MMA_BF16(a1[0], a[0], a[1], a[2], a[3], bx[0], bx[1]);
                MMA_BF16(a1[1], a[0], a[1], a[2], a[3], bx[2], bx[3]);
                MMA_BF16(a1[2], a[0], a[1], a[2], a[3], by[0], by[1]);
            }
            #pragma unroll
            for (int nt = 0; nt < 3; nt++) {
                int lr = wm * 16 + (lane >> 2);
                int lc = wn * 24 + nt * 8 + (lane & 3) * 2;
                int gcol = c * 48 + lc;
                float bf0 = bias1[gcol], bf1 = bias1[gcol + 1];
                float v0 = a1[nt][0] + bf0, v1 = a1[nt][1] + bf1;
                float v2 = a1[nt][2] + bf0, v3 = a1[nt][3] + bf1;
                v0 = 0.5f * v0 * (1.0f + erff(v0 * 0.70710678118654752f));
                v1 = 0.5f * v1 * (1.0f + erff(v1 * 0.70710678118654752f));
                v2 = 0.5f * v2 * (1.0f + erff(v2 * 0.70710678118654752f));
                v3 = 0.5f * v3 * (1.0f + erff(v3 * 0.70710678118654752f));
                __nv_bfloat162 p0, p1;
                p0.x = __float2bfloat16(v0); p0.y = __float2bfloat16(v1);
                p1.x = __float2bfloat16(v2); p1.y = __float2bfloat16(v3);
                *(__nv_bfloat162*)(sQKV + lr * STRQ + lc)       = p0;
                *(__nv_bfloat162*)(sQKV + (lr + 8) * STRQ + lc) = p1;
            }
        }
        __syncthreads();
        // load W2 chunk: 96 rows x 48 K-cols (stride 56)
        for (int gi = tid; gi < 576; gi += 512) {
            int row = gi / 6, q = gi - row * 6;
            *(uint4*)(pW + row * 56 + q * 8) =
                *(const uint4*)(w2 + (size_t)row * 384 + c * 48 + q * 8);
        }
        __syncthreads();
        // fc2 partial: (128x48)@(96x48)^T accumulate
        #pragma unroll
        for (int ks = 0; ks < 3; ks++) {
            uint32_t a[4], bf[3][4];
            LDSM_X4(a[0], a[1], a[2], a[3], ah + ks * 32);
            #pragma unroll
            for (int ng = 0; ng < 3; ng++)
                LDSM_X4(bf[ng][0], bf[ng][1], bf[ng][2], bf[ng][3],
                        b2a + ng * (16 * 56 * 2) + ks * 32);
            #pragma unroll
            for (int nt = 0; nt < 6; nt++) {
                int ng = nt >> 1, pr = (nt & 1) * 2;
                MMA_BF16(acc2[nt], a[0], a[1], a[2], a[3], bf[ng][pr], bf[ng][pr + 1]);
            }
        }
    }

    // ---- phase 6: out = fc2 + bias2 + y, scatter natural order (fp32) ----
    #pragma unroll
    for (int hh = 0; hh < 2; hh++) {
        int lr = wm * 16 + (lane >> 2) + hh * 8;
        int dt = lr >> 6, dh = (lr >> 3) & 7, dw = lr & 7;
        int t = tb * 2 + dt, h = hb * 8 + dh, w = wb * 8 + dw;
        int ti = (t + 1) & 7, hi = (h + 4) & 127, wi = (w + 4) & 127;
        size_t m = ((size_t)((bi * 8 + ti) * 128 + hi)) * 128 + wi;
        #pragma unroll
        for (int nt = 0; nt < 6; nt++) {
            int lc = wn * 48 + nt * 8 + (lane & 3) * 2;
            float2 yv = *(float2*)(yf + lr * 148 + 48 + lc);
            float v0 = acc2[nt][hh * 2 + 0] + bias2[lc]     + yv.x;
            float v1 = acc2[nt][hh * 2 + 1] + bias2[lc + 1] + yv.y;
            *(float2*)(out + m * 96 + lc) = make_float2(v0, v1);
        }
    }
}

// ---------------- launch ----------------
extern "C" void kernel_launch(void* const* d_in, const int* in_sizes, int n_in,
                              void* d_out, int out_size)
{
    const float* x      = (const float*)d_in[0];
    const float* g1     = (const float*)d_in[2];
    const float* b1     = (const float*)d_in[3];
    const float* w_qkv  = (const float*)d_in[4];
    const float* b_qkv  = (const float*)d_in[5];
    const float* w_proj = (const float*)d_in[6];
    const float* b_proj = (const float*)d_in[7];
    const float* g2     = (const float*)d_in[8];
    const float* b2     = (const float*)d_in[9];
    const float* w_fc1  = (const float*)d_in[10];
    const float* b_fc1  = (const float*)d_in[11];
    const float* w_fc2  = (const float*)d_in[12];
    const float* b_fc2  = (const float*)d_in[13];
    float* out = (float*)d_out;

    __nv_bfloat16 *p_wb;
    cudaGetSymbolAddress((void**)&p_wb, g_wb);

    static bool attr_set = false;
    if (!attr_set) {
        cudaFuncSetAttribute(mono_kernel,
                             cudaFuncAttributeMaxDynamicSharedMemorySize, SMEM_MONO);
        attr_set = true;
    }

    convert_w<<<(110592 + 255) / 256, 256>>>(w_qkv, w_proj, w_fc1, w_fc2, p_wb);

    mono_kernel<<<NWIN, 512, SMEM_MONO>>>(
        x, g1, b1,
        p_wb + WB_QKV, b_qkv, p_wb + WB_PROJ, b_proj,
        g2, b2,
        p_wb + WB_FC1, b_fc1, p_wb + WB_FC2, b_fc2,
        out);
}

// round 12
// speedup vs baseline: 1.3624x; 1.3129x over previous
#include <cuda_runtime.h>
#include <cuda_bf16.h>
#include <math.h>
#include <stdint.h>

// ---------------- problem constants ----------------
#define NTOK (2*8*128*128)          // 262144 tokens
#define NWIN (NTOK/128)             // 2048 windows
#define SCALE 0.25f

// ---------------- scratch ----------------
__device__ __nv_bfloat16 g_wb [110592];              // bf16 weights
__device__ float         g_y  [(size_t)NTOK * 96];   // first residual (natural, fp32)

#define WB_QKV  0
#define WB_PROJ 27648
#define WB_FC1  36864
#define WB_FC2  73728

static __device__ __forceinline__ uint32_t s2u(const void* p) {
    return (uint32_t)__cvta_generic_to_shared(p);
}

#define LDSM_X4(r0,r1,r2,r3,addr) \
    asm volatile("ldmatrix.sync.aligned.m8n8.x4.shared.b16 {%0,%1,%2,%3}, [%4];" \
        : "=r"(r0),"=r"(r1),"=r"(r2),"=r"(r3) : "r"(addr))

#define LDSM_X4_T(r0,r1,r2,r3,addr) \
    asm volatile("ldmatrix.sync.aligned.m8n8.x4.trans.shared.b16 {%0,%1,%2,%3}, [%4];" \
        : "=r"(r0),"=r"(r1),"=r"(r2),"=r"(r3) : "r"(addr))

#define MMA_BF16(c,a0,a1,a2,a3,b0,b1) \
    asm volatile("mma.sync.aligned.m16n8k16.row.col.f32.bf16.bf16.f32 " \
        "{%0,%1,%2,%3},{%4,%5,%6,%7},{%8,%9},{%0,%1,%2,%3};" \
        : "+f"(c[0]),"+f"(c[1]),"+f"(c[2]),"+f"(c[3]) \
        : "r"(a0),"r"(a1),"r"(a2),"r"(a3),"r"(b0),"r"(b1))

#define CP_ASYNC16(dst,src) \
    asm volatile("cp.async.cg.shared.global [%0], [%1], 16;" :: "r"(dst), "l"(src))
#define CP_COMMIT() asm volatile("cp.async.commit_group;")
#define CP_WAIT0()  asm volatile("cp.async.wait_group 0;")

static __device__ __forceinline__ float gelu_t(float v) {
    float u = 0.7978845608028654f * v * fmaf(0.044715f, v * v, 1.0f);
    float t;
    asm("tanh.approx.f32 %0, %1;" : "=f"(t) : "f"(u));
    return 0.5f * v * (1.0f + t);
}

// ---------------- weight conversion fp32 -> bf16 ----------------
__global__ void convert_w(const float* __restrict__ wq, const float* __restrict__ wp,
                          const float* __restrict__ w1, const float* __restrict__ w2,
                          __nv_bfloat16* __restrict__ out)
{
    int i = blockIdx.x * 256 + threadIdx.x;
    if (i < 27648)       out[i] = __float2bfloat16(wq[i]);
    else if (i < 36864)  out[i] = __float2bfloat16(wp[i - 27648]);
    else if (i < 73728)  out[i] = __float2bfloat16(w1[i - 36864]);
    else if (i < 110592) out[i] = __float2bfloat16(w2[i - 73728]);
}

// ================= MONO kernel, 512 threads, 2 CTAs/SM =================
// smem (bf16 elems):
//   sQKV [0, 37888)      128x296: q-slots cols 0..95 (LN1 -> q -> attn-out -> MLP hidden),
//                        kv-slots cols 96..287 (k,v -> y fp32 staging -> W1/W2 buffers)
//   pW   [37888, 56576)  5376 weight chunk (QKV/proj) + LN2 @ +5376 (128x104)
//   lab  @ elem 56576    128 ints
#define STRQ 296
#define OFF_W   37888
#define OFF_LN2 (37888 + 5376)
#define OFF_LAB 56576
#define SMEM_MONO 113664

__global__ __launch_bounds__(512, 2) void mono_kernel(
    const float* __restrict__ x,
    const float* __restrict__ g1, const float* __restrict__ b1,
    const __nv_bfloat16* __restrict__ wqkv, const float* __restrict__ b_qkv,
    const __nv_bfloat16* __restrict__ wproj, const float* __restrict__ b_proj,
    const float* __restrict__ g2, const float* __restrict__ b2,
    const __nv_bfloat16* __restrict__ w1, const float* __restrict__ bias1,
    const __nv_bfloat16* __restrict__ w2, const float* __restrict__ bias2,
    float* __restrict__ yscr,
    float* __restrict__ out)
{
    extern __shared__ __align__(16) char smem_raw[];
    __nv_bfloat16* sQKV = (__nv_bfloat16*)smem_raw;
    __nv_bfloat16* pW   = sQKV + OFF_W;
    __nv_bfloat16* pLN2 = sQKV + OFF_LN2;
    int* lab = (int*)(sQKV + OFF_LAB);
    float* yf = (float*)smem_raw;    // y staging: yf[row*148 + 48 + col]

    const int tid  = threadIdx.x;
    const int lane = tid & 31;
    const int warp = tid >> 5;        // 16 warps
    const int wm = warp & 7, wn = warp >> 3;   // 8m x 2n

    const int win = blockIdx.x;
    const int wr = win & 1023;
    const int tb = wr >> 8, hb = (wr >> 4) & 15, wb = wr & 15;
    const int bi = win >> 10;

    // ---- phase 0: labels + LN1 (shift gather) -> q-slots ----
    if (tid < 128) {
        int n = tid;
        int lt = (tb == 3) ? (n >> 6) : 0;
        int lh = (hb == 15) ? ((n >> 5) & 1) : 0;
        int lw = (wb == 15) ? ((n >> 2) & 1) : 0;
        lab[n] = lt | (lh << 1) | (lw << 2);
    }
    for (int tok = warp; tok < 128; tok += 16) {
        int dt = tok >> 6, dh = (tok >> 3) & 7, dw = tok & 7;
        int t = tb * 2 + dt, h = hb * 8 + dh, w = wb * 8 + dw;
        int ti = (t + 1) & 7, hi = (h + 4) & 127, wi = (w + 4) & 127;
        size_t src = ((size_t)((bi * 8 + ti) * 128 + hi)) * 128 + wi;
        const float* row = x + src * 96;
        float v0 = row[lane], v1 = row[lane + 32], v2 = row[lane + 64];
        float s  = v0 + v1 + v2;
        float s2 = v0 * v0 + v1 * v1 + v2 * v2;
        #pragma unroll
        for (int o = 16; o; o >>= 1) {
            s  += __shfl_xor_sync(0xffffffffu, s,  o);
            s2 += __shfl_xor_sync(0xffffffffu, s2, o);
        }
        float mean = s * (1.0f / 96.0f);
        float var  = s2 * (1.0f / 96.0f) - mean * mean;
        float rstd = rsqrtf(var + 1e-5f);
        __nv_bfloat16* orow = sQKV + tok * STRQ;
        orow[lane]      = __float2bfloat16((v0 - mean) * rstd * g1[lane]      + b1[lane]);
        orow[lane + 32] = __float2bfloat16((v1 - mean) * rstd * g1[lane + 32] + b1[lane + 32]);
        orow[lane + 64] = __float2bfloat16((v2 - mean) * rstd * g1[lane + 64] + b1[lane + 64]);
    }

    // ---- phase 1: QKV GEMM in 3 chunks (k, v, then q last) ----
    const uint32_t aq   = s2u(sQKV + (wm * 16 + (lane & 15)) * STRQ + (lane >> 4) * 8);
    const uint32_t bw48 = s2u(pW + (wn * 48 + ((lane >> 4) << 3) + (lane & 7)) * 104
                                 + ((lane >> 3) & 1) * 8);
    {
        const int ccs[3] = {1, 2, 0};
        #pragma unroll
        for (int ci = 0; ci < 3; ci++) {
            int cc = ccs[ci];
            __syncthreads();
            for (int gi = tid; gi < 1152; gi += 512) {
                int row = gi / 12, q = gi - row * 12;
                *(uint4*)(pW + row * 104 + q * 8) =
                    *(const uint4*)(wqkv + (size_t)(cc * 96 + row) * 96 + q * 8);
            }
            __syncthreads();
            float acc[6][4] = {};
            #pragma unroll
            for (int ks = 0; ks < 6; ks++) {
                uint32_t a[4], bf[3][4];
                LDSM_X4(a[0], a[1], a[2], a[3], aq + ks * 32);
                #pragma unroll
                for (int ng = 0; ng < 3; ng++)
                    LDSM_X4(bf[ng][0], bf[ng][1], bf[ng][2], bf[ng][3],
                            bw48 + ng * (16 * 104 * 2) + ks * 32);
                #pragma unroll
                for (int nt = 0; nt < 6; nt++) {
                    int ng = nt >> 1, pr = (nt & 1) * 2;
                    MMA_BF16(acc[nt], a[0], a[1], a[2], a[3], bf[ng][pr], bf[ng][pr + 1]);
                }
            }
            if (cc == 0) __syncthreads();   // all warps done reading LN1 (q-slots)
            #pragma unroll
            for (int nt = 0; nt < 6; nt++) {
                int lr  = wm * 16 + (lane >> 2);
                int lc  = wn * 48 + nt * 8 + (lane & 3) * 2;
                int gcol = cc * 96 + lc;
                float bf0 = b_qkv[gcol], bf1 = b_qkv[gcol + 1];
                __nv_bfloat162 p0, p1;
                p0.x = __float2bfloat16(acc[nt][0] + bf0);
                p0.y = __float2bfloat16(acc[nt][1] + bf1);
                p1.x = __float2bfloat16(acc[nt][2] + bf0);
                p1.y = __float2bfloat16(acc[nt][3] + bf1);
                *(__nv_bfloat162*)(sQKV + lr * STRQ + gcol)       = p0;
                *(__nv_bfloat162*)(sQKV + (lr + 8) * STRQ + gcol) = p1;
            }
        }
    }
    __syncthreads();

    // ---- phase 2: attention (48 units = 6 heads x 8 row-tiles) + Wproj prefetch ----
    for (int gi = tid; gi < 1152; gi += 512) {
        int row = gi / 12, q = gi - row * 12;
        *(uint4*)(pW + row * 104 + q * 8) = *(const uint4*)(wproj + (size_t)row * 96 + q * 8);
    }
    {
        const bool masked = (tb == 3) || (hb == 15) || (wb == 15);
        const uint32_t ONEB = 0x3F803F80u;   // bf16x2 {1.0, 1.0}
        for (int u = warp; u < 48; u += 16) {
            int head = u >> 3, rtile = u & 7;
            int hoff = head * 16, r0 = rtile * 16;
            uint32_t qa[4];
            LDSM_X4(qa[0], qa[1], qa[2], qa[3],
                    s2u(sQKV + (r0 + (lane & 15)) * STRQ + hoff + (lane >> 4) * 8));
            const int lr0 = lab[r0 + (lane >> 2)];
            const int lr1 = lab[r0 + 8 + (lane >> 2)];
            const uint32_t kaddr = s2u(sQKV + (((lane >> 4) << 3) + (lane & 7)) * STRQ
                                            + 96 + hoff + ((lane >> 3) & 1) * 8);
            const uint32_t vaddr = s2u(sQKV + (lane & 15) * STRQ + 192 + hoff + (lane >> 4) * 8);
            float o0[4] = {}, o1[4] = {}, osum[4] = {};
            #pragma unroll
            for (int jg = 0; jg < 8; jg++) {
                uint32_t kb[4];
                LDSM_X4(kb[0], kb[1], kb[2], kb[3], kaddr + jg * (16 * STRQ * 2));
                float c0[4] = {}, c1[4] = {};
                MMA_BF16(c0, qa[0], qa[1], qa[2], qa[3], kb[0], kb[1]);
                MMA_BF16(c1, qa[0], qa[1], qa[2], qa[3], kb[2], kb[3]);
                int colA = jg * 16 + (lane & 3) * 2;
                int colB = colA + 8;
                float e00 = __expf(SCALE * c0[0]);
                float e01 = __expf(SCALE * c0[1]);
                float e10 = __expf(SCALE * c0[2]);
                float e11 = __expf(SCALE * c0[3]);
                float f00 = __expf(SCALE * c1[0]);
                float f01 = __expf(SCALE * c1[1]);
                float f10 = __expf(SCALE * c1[2]);
                float f11 = __expf(SCALE * c1[3]);
                if (masked) {
                    int la0 = lab[colA], la1 = lab[colA + 1];
                    int lb0 = lab[colB], lb1 = lab[colB + 1];
                    e00 = (la0 == lr0) ? e00 : 0.0f;
                    e01 = (la1 == lr0) ? e01 : 0.0f;
                    e10 = (la0 == lr1) ? e10 : 0.0f;
                    e11 = (la1 == lr1) ? e11 : 0.0f;
                    f00 = (lb0 == lr0) ? f00 : 0.0f;
                    f01 = (lb1 == lr0) ? f01 : 0.0f;
                    f10 = (lb0 == lr1) ? f10 : 0.0f;
                    f11 = (lb1 == lr1) ? f11 : 0.0f;
                }
                __nv_bfloat162 a0 = __floats2bfloat162_rn(e00, e01);
                __nv_bfloat162 a1 = __floats2bfloat162_rn(e10, e11);
                __nv_bfloat162 a2 = __floats2bfloat162_rn(f00, f01);
                __nv_bfloat162 a3 = __floats2bfloat162_rn(f10, f11);
                uint32_t vb[4];
                LDSM_X4_T(vb[0], vb[1], vb[2], vb[3], vaddr + jg * (16 * STRQ * 2));
                MMA_BF16(o0, *(uint32_t*)&a0, *(uint32_t*)&a1, *(uint32_t*)&a2, *(uint32_t*)&a3,
                         vb[0], vb[1]);
                MMA_BF16(o1, *(uint32_t*)&a0, *(uint32_t*)&a1, *(uint32_t*)&a2, *(uint32_t*)&a3,
                         vb[2], vb[3]);
                MMA_BF16(osum, *(uint32_t*)&a0, *(uint32_t*)&a1, *(uint32_t*)&a2, *(uint32_t*)&a3,
                         ONEB, ONEB);
            }
            float inv0 = 1.0f / osum[0];
            float inv1 = 1.0f / osum[2];
            // write attn-out into q-slots (own rows/head only)
            int r = r0 + (lane >> 2);
            #pragma unroll
            for (int nt = 0; nt < 2; nt++) {
                int col = hoff + nt * 8 + (lane & 3) * 2;
                float* o = nt ? o1 : o0;
                __nv_bfloat162 w0 = __floats2bfloat162_rn(o[0] * inv0, o[1] * inv0);
                __nv_bfloat162 w1 = __floats2bfloat162_rn(o[2] * inv1, o[3] * inv1);
                *(__nv_bfloat162*)(sQKV + r * STRQ + col)       = w0;
                *(__nv_bfloat162*)(sQKV + (r + 8) * STRQ + col) = w1;
            }
        }
    }
    __syncthreads();

    // ---- phase 3: proj GEMM (A = attn-out q-slots, B = Wproj) -> yf staging ----
    {
        float acc[6][4] = {};
        #pragma unroll
        for (int ks = 0; ks < 6; ks++) {
            uint32_t a[4], bf[3][4];
            LDSM_X4(a[0], a[1], a[2], a[3], aq + ks * 32);
            #pragma unroll
            for (int ng = 0; ng < 3; ng++)
                LDSM_X4(bf[ng][0], bf[ng][1], bf[ng][2], bf[ng][3],
                        bw48 + ng * (16 * 104 * 2) + ks * 32);
            #pragma unroll
            for (int nt = 0; nt < 6; nt++) {
                int ng = nt >> 1, pr = (nt & 1) * 2;
                MMA_BF16(acc[nt], a[0], a[1], a[2], a[3], bf[ng][pr], bf[ng][pr + 1]);
            }
        }
        #pragma unroll
        for (int nt = 0; nt < 6; nt++) {
            int lr = wm * 16 + (lane >> 2);
            int lc = wn * 48 + nt * 8 + (lane & 3) * 2;
            float bf0 = b_proj[lc], bf1 = b_proj[lc + 1];
            yf[lr * 148 + 48 + lc]           = acc[nt][0] + bf0;
            yf[lr * 148 + 48 + lc + 1]       = acc[nt][1] + bf1;
            yf[(lr + 8) * 148 + 48 + lc]     = acc[nt][2] + bf0;
            yf[(lr + 8) * 148 + 48 + lc + 1] = acc[nt][3] + bf1;
        }
    }
    __syncthreads();

    // ---- phase 4: y = proj + x -> GMEM scratch (natural order); LN2 -> pLN2 ----
    for (int tok = warp; tok < 128; tok += 16) {
        int dt = tok >> 6, dh = (tok >> 3) & 7, dw = tok & 7;
        int t = tb * 2 + dt, h = hb * 8 + dh, w = wb * 8 + dw;
        int ti = (t + 1) & 7, hi = (h + 4) & 127, wi = (w + 4) & 127;
        size_t m = ((size_t)((bi * 8 + ti) * 128 + hi)) * 128 + wi;
        const float* xrow = x + m * 96;
        const float* yrow = yf + tok * 148 + 48;
        float v0 = yrow[lane]      + xrow[lane];
        float v1 = yrow[lane + 32] + xrow[lane + 32];
        float v2 = yrow[lane + 64] + xrow[lane + 64];
        float* gy = yscr + m * 96;
        gy[lane]      = v0;
        gy[lane + 32] = v1;
        gy[lane + 64] = v2;
        float s  = v0 + v1 + v2;
        float s2 = v0 * v0 + v1 * v1 + v2 * v2;
        #pragma unroll
        for (int o = 16; o; o >>= 1) {
            s  += __shfl_xor_sync(0xffffffffu, s,  o);
            s2 += __shfl_xor_sync(0xffffffffu, s2, o);
        }
        float mean = s * (1.0f / 96.0f);
        float var  = s2 * (1.0f / 96.0f) - mean * mean;
        float rstd = rsqrtf(var + 1e-5f);
        __nv_bfloat16* orow = pLN2 + tok * 104;
        orow[lane]      = __float2bfloat16((v0 - mean) * rstd * g2[lane]      + b2[lane]);
        orow[lane + 32] = __float2bfloat16((v1 - mean) * rstd * g2[lane + 32] + b2[lane + 32]);
        orow[lane + 64] = __float2bfloat16((v2 - mean) * rstd * g2[lane + 64] + b2[lane + 64]);
    }
    __syncthreads();   // yf fully consumed -> kv region free for weight buffers

    // ---- phase 5: MLP, 6 chunks of 64, double-buffered weights (cp.async) ----
    // bufW1: 64 rows x 96 cols at sQKV[row*STRQ + 96]; bufW2: 96 rows x 64 cols at +192
    float acc2[6][4] = {};
    const uint32_t aln = s2u(pLN2 + (wm * 16 + (lane & 15)) * 104 + (lane >> 4) * 8);
    const uint32_t ah2 = s2u(sQKV + (wm * 16 + (lane & 15)) * STRQ + (lane >> 4) * 8);
    const uint32_t bw1 = s2u(sQKV + 96 + (wn * 32 + ((lane >> 4) << 3) + (lane & 7)) * STRQ
                                  + ((lane >> 3) & 1) * 8);
    const uint32_t bw2 = s2u(sQKV + 192 + (wn * 48 + ((lane >> 4) << 3) + (lane & 7)) * STRQ
                                  + ((lane >> 3) & 1) * 8);

    // prefetch W1 chunk 0
    for (int gi = tid; gi < 768; gi += 512) {
        int row = gi >> 3 ? gi / 12 : gi / 12, q = gi - (gi / 12) * 12;
        row = gi / 12;
        CP_ASYNC16(s2u(sQKV + row * STRQ + 96 + q * 8),
                   (const void*)(w1 + (size_t)row * 96 + q * 8));
    }
    CP_COMMIT();

    for (int c = 0; c < 6; c++) {
        CP_WAIT0();
        __syncthreads();   // W1c ready; hidden free (prev fc2 done)
        // prefetch W2 chunk c -> bufW2
        for (int gi = tid; gi < 768; gi += 512) {
            int row = gi >> 3, q = gi & 7;
            CP_ASYNC16(s2u(sQKV + row * STRQ + 192 + q * 8),
                       (const void*)(w2 + (size_t)row * 384 + c * 64 + q * 8));
        }
        CP_COMMIT();
        // fc1 chunk: (128x96)@(64x96)^T + bias + GELU -> hidden (q-slots cols 0..63)
        {
            float a1[4][4] = {};
            #pragma unroll
            for (int ks = 0; ks < 6; ks++) {
                uint32_t a[4], bf[2][4];
                LDSM_X4(a[0], a[1], a[2], a[3], aln + ks * 32);
                #pragma unroll
                for (int ng = 0; ng < 2; ng++)
                    LDSM_X4(bf[ng][0], bf[ng][1], bf[ng][2], bf[ng][3],
                            bw1 + ng * (16 * STRQ * 2) + ks * 32);
                #pragma unroll
                for (int nt = 0; nt < 4; nt++) {
                    int ng = nt >> 1, pr = (nt & 1) * 2;
                    MMA_BF16(a1[nt], a[0], a[1], a[2], a[3], bf[ng][pr], bf[ng][pr + 1]);
                }
            }
            #pragma unroll
            for (int nt = 0; nt < 4; nt++) {
                int lr = wm * 16 + (lane >> 2);
                int lc = wn * 32 + nt * 8 + (lane & 3) * 2;
                int gcol = c * 64 + lc;
                float bf0 = bias1[gcol], bf1 = bias1[gcol + 1];
                float v0 = gelu_t(a1[nt][0] + bf0);
                float v1 = gelu_t(a1[nt][1] + bf1);
                float v2 = gelu_t(a1[nt][2] + bf0);
                float v3 = gelu_t(a1[nt][3] + bf1);
                __nv_bfloat162 p0, p1;
                p0.x = __float2bfloat16(v0); p0.y = __float2bfloat16(v1);
                p1.x = __float2bfloat16(v2); p1.y = __float2bfloat16(v3);
                *(__nv_bfloat162*)(sQKV + lr * STRQ + lc)       = p0;
                *(__nv_bfloat162*)(sQKV + (lr + 8) * STRQ + lc) = p1;
            }
        }
        CP_WAIT0();
        __syncthreads();   // W2c ready; hidden ready; bufW1 free
        // prefetch W1 chunk c+1 -> bufW1 (overlaps fc2)
        if (c < 5) {
            for (int gi = tid; gi < 768; gi += 512) {
                int row = gi / 12, q = gi - (gi / 12) * 12;
                CP_ASYNC16(s2u(sQKV + row * STRQ + 96 + q * 8),
                           (const void*)(w1 + (size_t)((c + 1) * 64 + row) * 96 + q * 8));
            }
        }
        CP_COMMIT();
        // fc2 partial: (128x64)@(96x64)^T accumulate
        #pragma unroll
        for (int ks = 0; ks < 4; ks++) {
            uint32_t a[4], bf[3][4];
            LDSM_X4(a[0], a[1], a[2], a[3], ah2 + ks * 32);
            #pragma unroll
            for (int ng = 0; ng < 3; ng++)
                LDSM_X4(bf[ng][0], bf[ng][1], bf[ng][2], bf[ng][3],
                        bw2 + ng * (16 * STRQ * 2) + ks * 32);
            #pragma unroll
            for (int nt = 0; nt < 6; nt++) {
                int ng = nt >> 1, pr = (nt & 1) * 2;
                MMA_BF16(acc2[nt], a[0], a[1], a[2], a[3], bf[ng][pr], bf[ng][pr + 1]);
            }
        }
    }

    // ---- phase 6: out = fc2 + bias2 + y(gmem), scatter natural order (fp32) ----
    #pragma unroll
    for (int hh = 0; hh < 2; hh++) {
        int lr = wm * 16 + (lane >> 2) + hh * 8;
        int dt = lr >> 6, dh = (lr >> 3) & 7, dw = lr & 7;
        int t = tb * 2 + dt, h = hb * 8 + dh, w = wb * 8 + dw;
        int ti = (t + 1) & 7, hi = (h + 4) & 127, wi = (w + 4) & 127;
        size_t m = ((size_t)((bi * 8 + ti) * 128 + hi)) * 128 + wi;
        #pragma unroll
        for (int nt = 0; nt < 6; nt++) {
            int lc = wn * 48 + nt * 8 + (lane & 3) * 2;
            float2 yv = *(const float2*)(yscr + m * 96 + lc);
            float v0 = acc2[nt][hh * 2 + 0] + bias2[lc]     + yv.x;
            float v1 = acc2[nt][hh * 2 + 1] + bias2[lc + 1] + yv.y;
            *(float2*)(out + m * 96 + lc) = make_float2(v0, v1);
        }
    }
}

// ---------------- launch ----------------
extern "C" void kernel_launch(void* const* d_in, const int* in_sizes, int n_in,
                              void* d_out, int out_size)
{
    const float* x      = (const float*)d_in[0];
    const float* g1     = (const float*)d_in[2];
    const float* b1     = (const float*)d_in[3];
    const float* w_qkv  = (const float*)d_in[4];
    const float* b_qkv  = (const float*)d_in[5];
    const float* w_proj = (const float*)d_in[6];
    const float* b_proj = (const float*)d_in[7];
    const float* g2     = (const float*)d_in[8];
    const float* b2     = (const float*)d_in[9];
    const float* w_fc1  = (const float*)d_in[10];
    const float* b_fc1  = (const float*)d_in[11];
    const float* w_fc2  = (const float*)d_in[12];
    const float* b_fc2  = (const float*)d_in[13];
    float* out = (float*)d_out;

    __nv_bfloat16 *p_wb;
    float *p_y;
    cudaGetSymbolAddress((void**)&p_wb, g_wb);
    cudaGetSymbolAddress((void**)&p_y,  g_y);

    static bool attr_set = false;
    if (!attr_set) {
        cudaFuncSetAttribute(mono_kernel,
                             cudaFuncAttributeMaxDynamicSharedMemorySize, SMEM_MONO);
        attr_set = true;
    }

    convert_w<<<(110592 + 255) / 256, 256>>>(w_qkv, w_proj, w_fc1, w_fc2, p_wb);

    mono_kernel<<<NWIN, 512, SMEM_MONO>>>(
        x, g1, b1,
        p_wb + WB_QKV, b_qkv, p_wb + WB_PROJ, b_proj,
        g2, b2,
        p_wb + WB_FC1, b_fc1, p_wb + WB_FC2, b_fc2,
        p_y, out);
}

// round 13
// speedup vs baseline: 1.3872x; 1.0182x over previous
#include <cuda_runtime.h>
#include <cuda_bf16.h>
#include <math.h>
#include <stdint.h>

// ---------------- problem constants ----------------
#define NTOK (2*8*128*128)          // 262144 tokens
#define NWIN (NTOK/128)             // 2048 windows
// SCALE * log2(e) folded into q at QKV epilogue:
#define QSCALE 0.36067376022224085f

// ---------------- scratch ----------------
__device__ __nv_bfloat16 g_wb [110592];              // bf16 weights
__device__ float         g_y  [(size_t)NTOK * 96];   // first residual (natural, fp32)

#define WB_QKV  0
#define WB_PROJ 27648
#define WB_FC1  36864
#define WB_FC2  73728

static __device__ __forceinline__ uint32_t s2u(const void* p) {
    return (uint32_t)__cvta_generic_to_shared(p);
}

#define LDSM_X4(r0,r1,r2,r3,addr) \
    asm volatile("ldmatrix.sync.aligned.m8n8.x4.shared.b16 {%0,%1,%2,%3}, [%4];" \
        : "=r"(r0),"=r"(r1),"=r"(r2),"=r"(r3) : "r"(addr))

#define LDSM_X4_T(r0,r1,r2,r3,addr) \
    asm volatile("ldmatrix.sync.aligned.m8n8.x4.trans.shared.b16 {%0,%1,%2,%3}, [%4];" \
        : "=r"(r0),"=r"(r1),"=r"(r2),"=r"(r3) : "r"(addr))

#define MMA_BF16(c,a0,a1,a2,a3,b0,b1) \
    asm volatile("mma.sync.aligned.m16n8k16.row.col.f32.bf16.bf16.f32 " \
        "{%0,%1,%2,%3},{%4,%5,%6,%7},{%8,%9},{%0,%1,%2,%3};" \
        : "+f"(c[0]),"+f"(c[1]),"+f"(c[2]),"+f"(c[3]) \
        : "r"(a0),"r"(a1),"r"(a2),"r"(a3),"r"(b0),"r"(b1))

#define CP_ASYNC16(dst,src) \
    asm volatile("cp.async.cg.shared.global [%0], [%1], 16;" :: "r"(dst), "l"(src))
#define CP_COMMIT() asm volatile("cp.async.commit_group;")
#define CP_WAIT0()  asm volatile("cp.async.wait_group 0;")

static __device__ __forceinline__ float ex2f(float x) {
    float r;
    asm("ex2.approx.f32 %0, %1;" : "=f"(r) : "f"(x));
    return r;
}

static __device__ __forceinline__ float gelu_t(float v) {
    float u = 0.7978845608028654f * v * fmaf(0.044715f, v * v, 1.0f);
    float t;
    asm("tanh.approx.f32 %0, %1;" : "=f"(t) : "f"(u));
    return 0.5f * v * (1.0f + t);
}

// label bits of token n: {t: bit6, h: bit5, w: bit2}
static __device__ __forceinline__ int bits3(int n) {
    return ((n >> 6) & 1) | (((n >> 5) & 1) << 1) | (((n >> 2) & 1) << 2);
}

// ---------------- weight conversion fp32 -> bf16 ----------------
__global__ void convert_w(const float* __restrict__ wq, const float* __restrict__ wp,
                          const float* __restrict__ w1, const float* __restrict__ w2,
                          __nv_bfloat16* __restrict__ out)
{
    int i = blockIdx.x * 256 + threadIdx.x;
    if (i < 27648)       out[i] = __float2bfloat16(wq[i]);
    else if (i < 36864)  out[i] = __float2bfloat16(wp[i - 27648]);
    else if (i < 73728)  out[i] = __float2bfloat16(w1[i - 36864]);
    else if (i < 110592) out[i] = __float2bfloat16(w2[i - 73728]);
}

// ================= MONO kernel, 512 threads, 2 CTAs/SM =================
#define STRQ 296
#define OFF_W   37888
#define OFF_LN2 (37888 + 5376)
#define SMEM_MONO 113664

__global__ __launch_bounds__(512, 2) void mono_kernel(
    const float* __restrict__ x,
    const float* __restrict__ g1, const float* __restrict__ b1,
    const __nv_bfloat16* __restrict__ wqkv, const float* __restrict__ b_qkv,
    const __nv_bfloat16* __restrict__ wproj, const float* __restrict__ b_proj,
    const float* __restrict__ g2, const float* __restrict__ b2,
    const __nv_bfloat16* __restrict__ w1, const float* __restrict__ bias1,
    const __nv_bfloat16* __restrict__ w2, const float* __restrict__ bias2,
    float* __restrict__ yscr,
    float* __restrict__ out)
{
    extern __shared__ __align__(16) char smem_raw[];
    __nv_bfloat16* sQKV = (__nv_bfloat16*)smem_raw;
    __nv_bfloat16* pW   = sQKV + OFF_W;
    __nv_bfloat16* pLN2 = sQKV + OFF_LN2;
    float* yf = (float*)smem_raw;    // y staging: yf[row*148 + 48 + col]

    const int tid  = threadIdx.x;
    const int lane = tid & 31;
    const int warp = tid >> 5;        // 16 warps
    const int wm = warp & 7, wn = warp >> 3;   // 8m x 2n

    const int win = blockIdx.x;
    const int wr = win & 1023;
    const int tb = wr >> 8, hb = (wr >> 4) & 15, wb = wr & 15;
    const int bi = win >> 10;
    const int amask = ((tb == 3) ? 1 : 0) | ((hb == 15) ? 2 : 0) | ((wb == 15) ? 4 : 0);

    // ---- phase 0: prefetch k-chunk weights (cp.async) + LN1 (shift gather) ----
    for (int gi = tid; gi < 1152; gi += 512) {
        int row = gi / 12, q = gi - row * 12;
        CP_ASYNC16(s2u(pW + row * 104 + q * 8),
                   (const void*)(wqkv + (size_t)(96 + row) * 96 + q * 8));
    }
    CP_COMMIT();

    for (int tok = warp; tok < 128; tok += 16) {
        int dt = tok >> 6, dh = (tok >> 3) & 7, dw = tok & 7;
        int t = tb * 2 + dt, h = hb * 8 + dh, w = wb * 8 + dw;
        int ti = (t + 1) & 7, hi = (h + 4) & 127, wi = (w + 4) & 127;
        size_t src = ((size_t)((bi * 8 + ti) * 128 + hi)) * 128 + wi;
        const float* row = x + src * 96;
        float v0 = row[lane], v1 = row[lane + 32], v2 = row[lane + 64];
        float s  = v0 + v1 + v2;
        float s2 = v0 * v0 + v1 * v1 + v2 * v2;
        #pragma unroll
        for (int o = 16; o; o >>= 1) {
            s  += __shfl_xor_sync(0xffffffffu, s,  o);
            s2 += __shfl_xor_sync(0xffffffffu, s2, o);
        }
        float mean = s * (1.0f / 96.0f);
        float var  = s2 * (1.0f / 96.0f) - mean * mean;
        float rstd = rsqrtf(var + 1e-5f);
        __nv_bfloat16* orow = sQKV + tok * STRQ;
        orow[lane]      = __float2bfloat16((v0 - mean) * rstd * g1[lane]      + b1[lane]);
        orow[lane + 32] = __float2bfloat16((v1 - mean) * rstd * g1[lane + 32] + b1[lane + 32]);
        orow[lane + 64] = __float2bfloat16((v2 - mean) * rstd * g1[lane + 64] + b1[lane + 64]);
    }

    // ---- phase 1: QKV GEMM in 3 chunks (k, v, then q last; q pre-scaled) ----
    const uint32_t aq   = s2u(sQKV + (wm * 16 + (lane & 15)) * STRQ + (lane >> 4) * 8);
    const uint32_t bw48 = s2u(pW + (wn * 48 + ((lane >> 4) << 3) + (lane & 7)) * 104
                                 + ((lane >> 3) & 1) * 8);
    {
        const int ccs[3] = {1, 2, 0};
        #pragma unroll
        for (int ci = 0; ci < 3; ci++) {
            int cc = ccs[ci];
            if (ci > 0) {
                __syncthreads();    // all warps done reading pW for previous chunk
                for (int gi = tid; gi < 1152; gi += 512) {
                    int row = gi / 12, q = gi - row * 12;
                    CP_ASYNC16(s2u(pW + row * 104 + q * 8),
                               (const void*)(wqkv + (size_t)(cc * 96 + row) * 96 + q * 8));
                }
                CP_COMMIT();
            }
            CP_WAIT0();
            __syncthreads();
            float acc[6][4] = {};
            #pragma unroll
            for (int ks = 0; ks < 6; ks++) {
                uint32_t a[4], bf[3][4];
                LDSM_X4(a[0], a[1], a[2], a[3], aq + ks * 32);
                #pragma unroll
                for (int ng = 0; ng < 3; ng++)
                    LDSM_X4(bf[ng][0], bf[ng][1], bf[ng][2], bf[ng][3],
                            bw48 + ng * (16 * 104 * 2) + ks * 32);
                #pragma unroll
                for (int nt = 0; nt < 6; nt++) {
                    int ng = nt >> 1, pr = (nt & 1) * 2;
                    MMA_BF16(acc[nt], a[0], a[1], a[2], a[3], bf[ng][pr], bf[ng][pr + 1]);
                }
            }
            if (cc == 0) __syncthreads();   // all warps done reading LN1 (q-slots)
            const float qs = (cc == 0) ? QSCALE : 1.0f;
            #pragma unroll
            for (int nt = 0; nt < 6; nt++) {
                int lr  = wm * 16 + (lane >> 2);
                int lc  = wn * 48 + nt * 8 + (lane & 3) * 2;
                int gcol = cc * 96 + lc;
                float bf0 = b_qkv[gcol], bf1 = b_qkv[gcol + 1];
                __nv_bfloat162 p0, p1;
                p0.x = __float2bfloat16((acc[nt][0] + bf0) * qs);
                p0.y = __float2bfloat16((acc[nt][1] + bf1) * qs);
                p1.x = __float2bfloat16((acc[nt][2] + bf0) * qs);
                p1.y = __float2bfloat16((acc[nt][3] + bf1) * qs);
                *(__nv_bfloat162*)(sQKV + lr * STRQ + gcol)       = p0;
                *(__nv_bfloat162*)(sQKV + (lr + 8) * STRQ + gcol) = p1;
            }
        }
    }
    __syncthreads();

    // ---- phase 2: attention (48 units = 6 heads x 8 row-tiles) + Wproj prefetch ----
    for (int gi = tid; gi < 1152; gi += 512) {
        int row = gi / 12, q = gi - row * 12;
        CP_ASYNC16(s2u(pW + row * 104 + q * 8),
                   (const void*)(wproj + (size_t)row * 96 + q * 8));
    }
    CP_COMMIT();
    {
        const uint32_t ONEB = 0x3F803F80u;   // bf16x2 {1.0, 1.0}
        const int wbit = ((lane >> 1) & 1) << 2;   // column w-label bit (per lane)
        for (int u = warp; u < 48; u += 16) {
            int head = u >> 3, rtile = u & 7;
            int hoff = head * 16, r0 = rtile * 16;
            uint32_t qa[4];
            LDSM_X4(qa[0], qa[1], qa[2], qa[3],
                    s2u(sQKV + (r0 + (lane & 15)) * STRQ + hoff + (lane >> 4) * 8));
            const int rb0 = bits3(r0 + (lane >> 2));
            const int rb1 = bits3(r0 + 8 + (lane >> 2));
            const uint32_t kaddr = s2u(sQKV + (((lane >> 4) << 3) + (lane & 7)) * STRQ
                                            + 96 + hoff + ((lane >> 3) & 1) * 8);
            const uint32_t vaddr = s2u(sQKV + (lane & 15) * STRQ + 192 + hoff + (lane >> 4) * 8);
            float o0[4] = {}, o1[4] = {}, osum[4] = {};
            #pragma unroll
            for (int jg = 0; jg < 8; jg++) {
                uint32_t kb[4];
                LDSM_X4(kb[0], kb[1], kb[2], kb[3], kaddr + jg * (16 * STRQ * 2));
                float c0[4] = {}, c1[4] = {};
                MMA_BF16(c0, qa[0], qa[1], qa[2], qa[3], kb[0], kb[1]);
                MMA_BF16(c1, qa[0], qa[1], qa[2], qa[3], kb[2], kb[3]);
                // q pre-scaled by SCALE*log2e -> bare ex2
                __nv_bfloat162 a0 = __floats2bfloat162_rn(ex2f(c0[0]), ex2f(c0[1]));
                __nv_bfloat162 a1 = __floats2bfloat162_rn(ex2f(c0[2]), ex2f(c0[3]));
                __nv_bfloat162 a2 = __floats2bfloat162_rn(ex2f(c1[0]), ex2f(c1[1]));
                __nv_bfloat162 a3 = __floats2bfloat162_rn(ex2f(c1[2]), ex2f(c1[3]));
                uint32_t u0 = *(uint32_t*)&a0, u1 = *(uint32_t*)&a1;
                uint32_t u2 = *(uint32_t*)&a2, u3 = *(uint32_t*)&a3;
                if (amask) {
                    // all 4 cols of this jg share one label
                    int clab = ((jg >> 2) & 1) | (((jg >> 1) & 1) << 1) | wbit;
                    bool k0 = (((clab ^ rb0) & amask) == 0);
                    bool k1 = (((clab ^ rb1) & amask) == 0);
                    u0 = k0 ? u0 : 0u;  u2 = k0 ? u2 : 0u;
                    u1 = k1 ? u1 : 0u;  u3 = k1 ? u3 : 0u;
                }
                uint32_t vb[4];
                LDSM_X4_T(vb[0], vb[1], vb[2], vb[3], vaddr + jg * (16 * STRQ * 2));
                MMA_BF16(o0, u0, u1, u2, u3, vb[0], vb[1]);
                MMA_BF16(o1, u0, u1, u2, u3, vb[2], vb[3]);
                MMA_BF16(osum, u0, u1, u2, u3, ONEB, ONEB);
            }
            float inv0 = 1.0f / osum[0];
            float inv1 = 1.0f / osum[2];
            int r = r0 + (lane >> 2);
            #pragma unroll
            for (int nt = 0; nt < 2; nt++) {
                int col = hoff + nt * 8 + (lane & 3) * 2;
                float* o = nt ? o1 : o0;
                __nv_bfloat162 w0 = __floats2bfloat162_rn(o[0] * inv0, o[1] * inv0);
                __nv_bfloat162 w1 = __floats2bfloat162_rn(o[2] * inv1, o[3] * inv1);
                *(__nv_bfloat162*)(sQKV + r * STRQ + col)       = w0;
                *(__nv_bfloat162*)(sQKV + (r + 8) * STRQ + col) = w1;
            }
        }
    }
    CP_WAIT0();
    __syncthreads();

    // ---- phase 3: proj GEMM (A = attn-out q-slots, B = Wproj) -> yf staging ----
    {
        float acc[6][4] = {};
        #pragma unroll
        for (int ks = 0; ks < 6; ks++) {
            uint32_t a[4], bf[3][4];
            LDSM_X4(a[0], a[1], a[2], a[3], aq + ks * 32);
            #pragma unroll
            for (int ng = 0; ng < 3; ng++)
                LDSM_X4(bf[ng][0], bf[ng][1], bf[ng][2], bf[ng][3],
                        bw48 + ng * (16 * 104 * 2) + ks * 32);
            #pragma unroll
            for (int nt = 0; nt < 6; nt++) {
                int ng = nt >> 1, pr = (nt & 1) * 2;
                MMA_BF16(acc[nt], a[0], a[1], a[2], a[3], bf[ng][pr], bf[ng][pr + 1]);
            }
        }
        #pragma unroll
        for (int nt = 0; nt < 6; nt++) {
            int lr = wm * 16 + (lane >> 2);
            int lc = wn * 48 + nt * 8 + (lane & 3) * 2;
            float bf0 = b_proj[lc], bf1 = b_proj[lc + 1];
            yf[lr * 148 + 48 + lc]           = acc[nt][0] + bf0;
            yf[lr * 148 + 48 + lc + 1]       = acc[nt][1] + bf1;
            yf[(lr + 8) * 148 + 48 + lc]     = acc[nt][2] + bf0;
            yf[(lr + 8) * 148 + 48 + lc + 1] = acc[nt][3] + bf1;
        }
    }
    __syncthreads();

    // ---- phase 4: y = proj + x -> GMEM scratch (natural order); LN2 -> pLN2 ----
    for (int tok = warp; tok < 128; tok += 16) {
        int dt = tok >> 6, dh = (tok >> 3) & 7, dw = tok & 7;
        int t = tb * 2 + dt, h = hb * 8 + dh, w = wb * 8 + dw;
        int ti = (t + 1) & 7, hi = (h + 4) & 127, wi = (w + 4) & 127;
        size_t m = ((size_t)((bi * 8 + ti) * 128 + hi)) * 128 + wi;
        const float* xrow = x + m * 96;
        const float* yrow = yf + tok * 148 + 48;
        float v0 = yrow[lane]      + xrow[lane];
        float v1 = yrow[lane + 32] + xrow[lane + 32];
        float v2 = yrow[lane + 64] + xrow[lane + 64];
        float* gy = yscr + m * 96;
        gy[lane]      = v0;
        gy[lane + 32] = v1;
        gy[lane + 64] = v2;
        float s  = v0 + v1 + v2;
        float s2 = v0 * v0 + v1 * v1 + v2 * v2;
        #pragma unroll
        for (int o = 16; o; o >>= 1) {
            s  += __shfl_xor_sync(0xffffffffu, s,  o);
            s2 += __shfl_xor_sync(0xffffffffu, s2, o);
        }
        float mean = s * (1.0f / 96.0f);
        float var  = s2 * (1.0f / 96.0f) - mean * mean;
        float rstd = rsqrtf(var + 1e-5f);
        __nv_bfloat16* orow = pLN2 + tok * 104;
        orow[lane]      = __float2bfloat16((v0 - mean) * rstd * g2[lane]      + b2[lane]);
        orow[lane + 32] = __float2bfloat16((v1 - mean) * rstd * g2[lane + 32] + b2[lane + 32]);
        orow[lane + 64] = __float2bfloat16((v2 - mean) * rstd * g2[lane + 64] + b2[lane + 64]);
    }
    __syncthreads();   // yf fully consumed -> kv region free for weight buffers

    // ---- phase 5: MLP, 6 chunks of 64, double-buffered weights (cp.async) ----
    float acc2[6][4] = {};
    const uint32_t aln = s2u(pLN2 + (wm * 16 + (lane & 15)) * 104 + (lane >> 4) * 8);
    const uint32_t ah2 = s2u(sQKV + (wm * 16 + (lane & 15)) * STRQ + (lane >> 4) * 8);
    const uint32_t bw1 = s2u(sQKV + 96 + (wn * 32 + ((lane >> 4) << 3) + (lane & 7)) * STRQ
                                  + ((lane >> 3) & 1) * 8);
    const uint32_t bw2 = s2u(sQKV + 192 + (wn * 48 + ((lane >> 4) << 3) + (lane & 7)) * STRQ
                                  + ((lane >> 3) & 1) * 8);

    // prefetch W1 chunk 0
    for (int gi = tid; gi < 768; gi += 512) {
        int row = gi / 12, q = gi - (gi / 12) * 12;
        CP_ASYNC16(s2u(sQKV + row * STRQ + 96 + q * 8),
                   (const void*)(w1 + (size_t)row * 96 + q * 8));
    }
    CP_COMMIT();

    for (int c = 0; c < 6; c++) {
        CP_WAIT0();
        __syncthreads();   // W1c ready; hidden free (prev fc2 done)
        // prefetch W2 chunk c -> bufW2
        for (int gi = tid; gi < 768; gi += 512) {
            int row = gi >> 3, q = gi & 7;
            CP_ASYNC16(s2u(sQKV + row * STRQ + 192 + q * 8),
                       (const void*)(w2 + (size_t)row * 384 + c * 64 + q * 8));
        }
        CP_COMMIT();
        // fc1 chunk: (128x96)@(64x96)^T + bias + GELU -> hidden (q-slots cols 0..63)
        {
            float a1[4][4] = {};
            #pragma unroll
            for (int ks = 0; ks < 6; ks++) {
                uint32_t a[4], bf[2][4];
                LDSM_X4(a[0], a[1], a[2], a[3], aln + ks * 32);
                #pragma unroll
                for (int ng = 0; ng < 2; ng++)
                    LDSM_X4(bf[ng][0], bf[ng][1], bf[ng][2], bf[ng][3],
                            bw1 + ng * (16 * STRQ * 2) + ks * 32);
                #pragma unroll
                for (int nt = 0; nt < 4; nt++) {
                    int ng = nt >> 1, pr = (nt & 1) * 2;
                    MMA_BF16(a1[nt], a[0], a[1], a[2], a[3], bf[ng][pr], bf[ng][pr + 1]);
                }
            }
            #pragma unroll
            for (int nt = 0; nt < 4; nt++) {
                int lr = wm * 16 + (lane >> 2);
                int lc = wn * 32 + nt * 8 + (lane & 3) * 2;
                int gcol = c * 64 + lc;
                float bf0 = bias1[gcol], bf1 = bias1[gcol + 1];
                float v0 = gelu_t(a1[nt][0] + bf0);
                float v1 = gelu_t(a1[nt][1] + bf1);
                float v2 = gelu_t(a1[nt][2] + bf0);
                float v3 = gelu_t(a1[nt][3] + bf1);
                __nv_bfloat162 p0, p1;
                p0.x = __float2bfloat16(v0); p0.y = __float2bfloat16(v1);
                p1.x = __float2bfloat16(v2); p1.y = __float2bfloat16(v3);
                *(__nv_bfloat162*)(sQKV + lr * STRQ + lc)       = p0;
                *(__nv_bfloat162*)(sQKV + (lr + 8) * STRQ + lc) = p1;
            }
        }
        CP_WAIT0();
        __syncthreads();   // W2c ready; hidden ready; bufW1 free
        // prefetch W1 chunk c+1 -> bufW1 (overlaps fc2)
        if (c < 5) {
            for (int gi = tid; gi < 768; gi += 512) {
                int row = gi / 12, q = gi - (gi / 12) * 12;
                CP_ASYNC16(s2u(sQKV + row * STRQ + 96 + q * 8),
                           (const void*)(w1 + (size_t)((c + 1) * 64 + row) * 96 + q * 8));
            }
        }
        CP_COMMIT();
        // fc2 partial: (128x64)@(96x64)^T accumulate
        #pragma unroll
        for (int ks = 0; ks < 4; ks++) {
            uint32_t a[4], bf[3][4];
            LDSM_X4(a[0], a[1], a[2], a[3], ah2 + ks * 32);
            #pragma unroll
            for (int ng = 0; ng < 3; ng++)
                LDSM_X4(bf[ng][0], bf[ng][1], bf[ng][2], bf[ng][3],
                        bw2 + ng * (16 * STRQ * 2) + ks * 32);
            #pragma unroll
            for (int nt = 0; nt < 6; nt++) {
                int ng = nt >> 1, pr = (nt & 1) * 2;
                MMA_BF16(acc2[nt], a[0], a[1], a[2], a[3], bf[ng][pr], bf[ng][pr + 1]);
            }
        }
    }

    // ---- phase 6: out = fc2 + bias2 + y(gmem), scatter natural order (fp32) ----
    #pragma unroll
    for (int hh = 0; hh < 2; hh++) {
        int lr = wm * 16 + (lane >> 2) + hh * 8;
        int dt = lr >> 6, dh = (lr >> 3) & 7, dw = lr & 7;
        int t = tb * 2 + dt, h = hb * 8 + dh, w = wb * 8 + dw;
        int ti = (t + 1) & 7, hi = (h + 4) & 127, wi = (w + 4) & 127;
        size_t m = ((size_t)((bi * 8 + ti) * 128 + hi)) * 128 + wi;
        #pragma unroll
        for (int nt = 0; nt < 6; nt++) {
            int lc = wn * 48 + nt * 8 + (lane & 3) * 2;
            float2 yv = *(const float2*)(yscr + m * 96 + lc);
            float v0 = acc2[nt][hh * 2 + 0] + bias2[lc]     + yv.x;
            float v1 = acc2[nt][hh * 2 + 1] + bias2[lc + 1] + yv.y;
            *(float2*)(out + m * 96 + lc) = make_float2(v0, v1);
        }
    }
}

// ---------------- launch ----------------
extern "C" void kernel_launch(void* const* d_in, const int* in_sizes, int n_in,
                              void* d_out, int out_size)
{
    const float* x      = (const float*)d_in[0];
    const float* g1     = (const float*)d_in[2];
    const float* b1     = (const float*)d_in[3];
    const float* w_qkv  = (const float*)d_in[4];
    const float* b_qkv  = (const float*)d_in[5];
    const float* w_proj = (const float*)d_in[6];
    const float* b_proj = (const float*)d_in[7];
    const float* g2     = (const float*)d_in[8];
    const float* b2     = (const float*)d_in[9];
    const float* w_fc1  = (const float*)d_in[10];
    const float* b_fc1  = (const float*)d_in[11];
    const float* w_fc2  = (const float*)d_in[12];
    const float* b_fc2  = (const float*)d_in[13];
    float* out = (float*)d_out;

    __nv_bfloat16 *p_wb;
    float *p_y;
    cudaGetSymbolAddress((void**)&p_wb, g_wb);
    cudaGetSymbolAddress((void**)&p_y,  g_y);

    static bool attr_set = false;
    if (!attr_set) {
        cudaFuncSetAttribute(mono_kernel,
                             cudaFuncAttributeMaxDynamicSharedMemorySize, SMEM_MONO);
        attr_set = true;
    }

    convert_w<<<(110592 + 255) / 256, 256>>>(w_qkv, w_proj, w_fc1, w_fc2, p_wb);

    mono_kernel<<<NWIN, 512, SMEM_MONO>>>(
        x, g1, b1,
        p_wb + WB_QKV, b_qkv, p_wb + WB_PROJ, b_proj,
        g2, b2,
        p_wb + WB_FC1, b_fc1, p_wb + WB_FC2, b_fc2,
        p_y, out);
}

// round 15
// speedup vs baseline: 1.3937x; 1.0046x over previous
#include <cuda_runtime.h>
#include <cuda_bf16.h>
#include <math.h>
#include <stdint.h>

// ---------------- problem constants ----------------
#define NTOK (2*8*128*128)          // 262144 tokens
#define NWIN (NTOK/128)             // 2048 windows
// SCALE * log2(e) folded into q at QKV epilogue:
#define QSCALE 0.36067376022224085f

// ---------------- scratch ----------------
__device__ __nv_bfloat16 g_wb [110592];              // bf16 weights
__device__ float         g_y  [(size_t)NTOK * 96];   // first residual (natural, fp32)

#define WB_QKV  0
#define WB_PROJ 27648
#define WB_FC1  36864
#define WB_FC2  73728

static __device__ __forceinline__ uint32_t s2u(const void* p) {
    return (uint32_t)__cvta_generic_to_shared(p);
}

#define LDSM_X4(r0,r1,r2,r3,addr) \
    asm volatile("ldmatrix.sync.aligned.m8n8.x4.shared.b16 {%0,%1,%2,%3}, [%4];" \
        : "=r"(r0),"=r"(r1),"=r"(r2),"=r"(r3) : "r"(addr))

#define LDSM_X4_T(r0,r1,r2,r3,addr) \
    asm volatile("ldmatrix.sync.aligned.m8n8.x4.trans.shared.b16 {%0,%1,%2,%3}, [%4];" \
        : "=r"(r0),"=r"(r1),"=r"(r2),"=r"(r3) : "r"(addr))

#define MMA_BF16(c,a0,a1,a2,a3,b0,b1) \
    asm volatile("mma.sync.aligned.m16n8k16.row.col.f32.bf16.bf16.f32 " \
        "{%0,%1,%2,%3},{%4,%5,%6,%7},{%8,%9},{%0,%1,%2,%3};" \
        : "+f"(c[0]),"+f"(c[1]),"+f"(c[2]),"+f"(c[3]) \
        : "r"(a0),"r"(a1),"r"(a2),"r"(a3),"r"(b0),"r"(b1))

#define CP_ASYNC16(dst,src) \
    asm volatile("cp.async.cg.shared.global [%0], [%1], 16;" :: "r"(dst), "l"(src))
#define CP_COMMIT() asm volatile("cp.async.commit_group;")
#define CP_WAIT0()  asm volatile("cp.async.wait_group 0;")

static __device__ __forceinline__ float ex2f(float x) {
    float r;
    asm("ex2.approx.f32 %0, %1;" : "=f"(r) : "f"(x));
    return r;
}

static __device__ __forceinline__ float gelu_t(float v) {
    float u = 0.7978845608028654f * v * fmaf(0.044715f, v * v, 1.0f);
    float t;
    asm("tanh.approx.f32 %0, %1;" : "=f"(t) : "f"(u));
    return 0.5f * v * (1.0f + t);
}

// label bits of token n: {t: bit6, h: bit5, w: bit2}
static __device__ __forceinline__ int bits3(int n) {
    return ((n >> 6) & 1) | (((n >> 5) & 1) << 1) | (((n >> 2) & 1) << 2);
}

// ---------------- weight conversion fp32 -> bf16 ----------------
__global__ void convert_w(const float* __restrict__ wq, const float* __restrict__ wp,
                          const float* __restrict__ w1, const float* __restrict__ w2,
                          __nv_bfloat16* __restrict__ out)
{
    int i = blockIdx.x * 256 + threadIdx.x;
    if (i < 27648)       out[i] = __float2bfloat16(wq[i]);
    else if (i < 36864)  out[i] = __float2bfloat16(wp[i - 27648]);
    else if (i < 73728)  out[i] = __float2bfloat16(w1[i - 36864]);
    else if (i < 110592) out[i] = __float2bfloat16(w2[i - 73728]);
}

// ================= MONO kernel, 512 threads, 2 CTAs/SM =================
// smem (bf16 elems):
//   sQKV [0, 37888)      128x296: q-slots cols 0..95, kv-slots cols 96..287
//   pWa  [37888, 47872)  weight buffer (96x104)  -- k, then q, then Wproj
//   pLN2 [43264, 56576)  LN2 tile 128x104 (phase >= 4 only; pWa dead by then)
// v-chunk weights stage temporarily in the v-slots (cols 192..287) of sQKV.
#define STRQ 296
#define OFF_WA  37888
#define OFF_LN2 43264
#define SMEM_MONO 113664

__global__ __launch_bounds__(512, 2) void mono_kernel(
    const float* __restrict__ x,
    const float* __restrict__ g1, const float* __restrict__ b1,
    const __nv_bfloat16* __restrict__ wqkv, const float* __restrict__ b_qkv,
    const __nv_bfloat16* __restrict__ wproj, const float* __restrict__ b_proj,
    const float* __restrict__ g2, const float* __restrict__ b2,
    const __nv_bfloat16* __restrict__ w1, const float* __restrict__ bias1,
    const __nv_bfloat16* __restrict__ w2, const float* __restrict__ bias2,
    float* __restrict__ yscr,
    float* __restrict__ out)
{
    extern __shared__ __align__(16) char smem_raw[];
    __nv_bfloat16* sQKV = (__nv_bfloat16*)smem_raw;
    __nv_bfloat16* pWa  = sQKV + OFF_WA;
    __nv_bfloat16* pLN2 = sQKV + OFF_LN2;
    float* yf = (float*)smem_raw;       // y staging: yf[row*148 + 48 + col]

    const int tid  = threadIdx.x;
    const int lane = tid & 31;
    const int warp = tid >> 5;        // 16 warps
    const int wm = warp & 7, wn = warp >> 3;   // 8m x 2n

    const int win = blockIdx.x;
    const int wr = win & 1023;
    const int tb = wr >> 8, hb = (wr >> 4) & 15, wb = wr & 15;
    const int bi = win >> 10;
    const int amask = ((tb == 3) ? 1 : 0) | ((hb == 15) ? 2 : 0) | ((wb == 15) ? 4 : 0);

    // ---- phase 0: prefetch k-chunk weights -> pWa + LN1 (shift gather) ----
    for (int gi = tid; gi < 1152; gi += 512) {
        int row = gi / 12, q = gi - row * 12;
        CP_ASYNC16(s2u(pWa + row * 104 + q * 8),
                   (const void*)(wqkv + (size_t)(96 + row) * 96 + q * 8));
    }
    CP_COMMIT();

    for (int tok = warp; tok < 128; tok += 16) {
        int dt = tok >> 6, dh = (tok >> 3) & 7, dw = tok & 7;
        int t = tb * 2 + dt, h = hb * 8 + dh, w = wb * 8 + dw;
        int ti = (t + 1) & 7, hi = (h + 4) & 127, wi = (w + 4) & 127;
        size_t src = ((size_t)((bi * 8 + ti) * 128 + hi)) * 128 + wi;
        const float* row = x + src * 96;
        float v0 = row[lane], v1 = row[lane + 32], v2 = row[lane + 64];
        float s  = v0 + v1 + v2;
        float s2 = v0 * v0 + v1 * v1 + v2 * v2;
        #pragma unroll
        for (int o = 16; o; o >>= 1) {
            s  += __shfl_xor_sync(0xffffffffu, s,  o);
            s2 += __shfl_xor_sync(0xffffffffu, s2, o);
        }
        float mean = s * (1.0f / 96.0f);
        float var  = s2 * (1.0f / 96.0f) - mean * mean;
        float rstd = rsqrtf(var + 1e-5f);
        __nv_bfloat16* orow = sQKV + tok * STRQ;
        orow[lane]      = __float2bfloat16((v0 - mean) * rstd * g1[lane]      + b1[lane]);
        orow[lane + 32] = __float2bfloat16((v1 - mean) * rstd * g1[lane + 32] + b1[lane + 32]);
        orow[lane + 64] = __float2bfloat16((v2 - mean) * rstd * g1[lane + 64] + b1[lane + 64]);
    }

    // ---- phase 1: QKV GEMM (k, v, q), loads overlapped ----
    const uint32_t aq = s2u(sQKV + (wm * 16 + (lane & 15)) * STRQ + (lane >> 4) * 8);
    const uint32_t bwA = s2u(pWa + (wn * 48 + ((lane >> 4) << 3) + (lane & 7)) * 104
                                 + ((lane >> 3) & 1) * 8);
    // v-chunk weights staged in v-slots: row stride STRQ, base col 192
    const uint32_t bwV = s2u(sQKV + (wn * 48 + ((lane >> 4) << 3) + (lane & 7)) * STRQ
                                  + 192 + ((lane >> 3) & 1) * 8);

    // -- chunk k (weights in pWa) --
    {
        CP_WAIT0();
        __syncthreads();   // k weights + LN1 visible
        // prefetch v weights into the (empty) v-slots
        for (int gi = tid; gi < 1152; gi += 512) {
            int row = gi / 12, q = gi - row * 12;
            CP_ASYNC16(s2u(sQKV + row * STRQ + 192 + q * 8),
                       (const void*)(wqkv + (size_t)(192 + row) * 96 + q * 8));
        }
        CP_COMMIT();

        float acc[6][4] = {};
        #pragma unroll
        for (int ks = 0; ks < 6; ks++) {
            uint32_t a[4], bf[3][4];
            LDSM_X4(a[0], a[1], a[2], a[3], aq + ks * 32);
            #pragma unroll
            for (int ng = 0; ng < 3; ng++)
                LDSM_X4(bf[ng][0], bf[ng][1], bf[ng][2], bf[ng][3],
                        bwA + ng * (16 * 104 * 2) + ks * 32);
            #pragma unroll
            for (int nt = 0; nt < 6; nt++) {
                int ng = nt >> 1, pr = (nt & 1) * 2;
                MMA_BF16(acc[nt], a[0], a[1], a[2], a[3], bf[ng][pr], bf[ng][pr + 1]);
            }
        }
        #pragma unroll
        for (int nt = 0; nt < 6; nt++) {
            int lr = wm * 16 + (lane >> 2);
            int lc = wn * 48 + nt * 8 + (lane & 3) * 2;
            int gcol = 96 + lc;                       // k -> cols 96..191
            float bf0 = b_qkv[gcol], bf1 = b_qkv[gcol + 1];
            __nv_bfloat162 p0, p1;
            p0.x = __float2bfloat16(acc[nt][0] + bf0);
            p0.y = __float2bfloat16(acc[nt][1] + bf1);
            p1.x = __float2bfloat16(acc[nt][2] + bf0);
            p1.y = __float2bfloat16(acc[nt][3] + bf1);
            *(__nv_bfloat162*)(sQKV + lr * STRQ + gcol)       = p0;
            *(__nv_bfloat162*)(sQKV + (lr + 8) * STRQ + gcol) = p1;
        }
    }

    // -- chunk v (weights in v-slots) --
    {
        CP_WAIT0();
        __syncthreads();   // v weights visible; all warps done reading pWa (k)
        // prefetch q weights into pWa
        for (int gi = tid; gi < 1152; gi += 512) {
            int row = gi / 12, q = gi - row * 12;
            CP_ASYNC16(s2u(pWa + row * 104 + q * 8),
                       (const void*)(wqkv + (size_t)row * 96 + q * 8));
        }
        CP_COMMIT();

        float acc[6][4] = {};
        #pragma unroll
        for (int ks = 0; ks < 6; ks++) {
            uint32_t a[4], bf[3][4];
            LDSM_X4(a[0], a[1], a[2], a[3], aq + ks * 32);
            #pragma unroll
            for (int ng = 0; ng < 3; ng++)
                LDSM_X4(bf[ng][0], bf[ng][1], bf[ng][2], bf[ng][3],
                        bwV + ng * (16 * STRQ * 2) + ks * 32);
            #pragma unroll
            for (int nt = 0; nt < 6; nt++) {
                int ng = nt >> 1, pr = (nt & 1) * 2;
                MMA_BF16(acc[nt], a[0], a[1], a[2], a[3], bf[ng][pr], bf[ng][pr + 1]);
            }
        }
        __syncthreads();   // all warps done reading v-slot weights before overwrite
        #pragma unroll
        for (int nt = 0; nt < 6; nt++) {
            int lr = wm * 16 + (lane >> 2);
            int lc = wn * 48 + nt * 8 + (lane & 3) * 2;
            int gcol = 192 + lc;                      // v -> cols 192..287
            float bf0 = b_qkv[gcol], bf1 = b_qkv[gcol + 1];
            __nv_bfloat162 p0, p1;
            p0.x = __float2bfloat16(acc[nt][0] + bf0);
            p0.y = __float2bfloat16(acc[nt][1] + bf1);
            p1.x = __float2bfloat16(acc[nt][2] + bf0);
            p1.y = __float2bfloat16(acc[nt][3] + bf1);
            *(__nv_bfloat162*)(sQKV + lr * STRQ + gcol)       = p0;
            *(__nv_bfloat162*)(sQKV + (lr + 8) * STRQ + gcol) = p1;
        }
    }

    // -- chunk q (weights in pWa; output pre-scaled by QSCALE) --
    {
        CP_WAIT0();
        __syncthreads();   // q weights visible
        float acc[6][4] = {};
        #pragma unroll
        for (int ks = 0; ks < 6; ks++) {
            uint32_t a[4], bf[3][4];
            LDSM_X4(a[0], a[1], a[2], a[3], aq + ks * 32);
            #pragma unroll
            for (int ng = 0; ng < 3; ng++)
                LDSM_X4(bf[ng][0], bf[ng][1], bf[ng][2], bf[ng][3],
                        bwA + ng * (16 * 104 * 2) + ks * 32);
            #pragma unroll
            for (int nt = 0; nt < 6; nt++) {
                int ng = nt >> 1, pr = (nt & 1) * 2;
                MMA_BF16(acc[nt], a[0], a[1], a[2], a[3], bf[ng][pr], bf[ng][pr + 1]);
            }
        }
        __syncthreads();   // all warps done reading LN1 (q-slots)
        #pragma unroll
        for (int nt = 0; nt < 6; nt++) {
            int lr = wm * 16 + (lane >> 2);
            int lc = wn * 48 + nt * 8 + (lane & 3) * 2;
            float bf0 = b_qkv[lc], bf1 = b_qkv[lc + 1];
            __nv_bfloat162 p0, p1;
            p0.x = __float2bfloat16((acc[nt][0] + bf0) * QSCALE);
            p0.y = __float2bfloat16((acc[nt][1] + bf1) * QSCALE);
            p1.x = __float2bfloat16((acc[nt][2] + bf0) * QSCALE);
            p1.y = __float2bfloat16((acc[nt][3] + bf1) * QSCALE);
            *(__nv_bfloat162*)(sQKV + lr * STRQ + lc)       = p0;
            *(__nv_bfloat162*)(sQKV + (lr + 8) * STRQ + lc) = p1;
        }
    }
    __syncthreads();

    // ---- phase 2: attention + Wproj prefetch into pWa ----
    for (int gi = tid; gi < 1152; gi += 512) {
        int row = gi / 12, q = gi - row * 12;
        CP_ASYNC16(s2u(pWa + row * 104 + q * 8),
                   (const void*)(wproj + (size_t)row * 96 + q * 8));
    }
    CP_COMMIT();
    {
        const uint32_t ONEB = 0x3F803F80u;   // bf16x2 {1.0, 1.0}
        const int wbit = ((lane >> 1) & 1) << 2;   // column w-label bit (per lane)
        for (int u = warp; u < 48; u += 16) {
            int head = u >> 3, rtile = u & 7;
            int hoff = head * 16, r0 = rtile * 16;
            uint32_t qa[4];
            LDSM_X4(qa[0], qa[1], qa[2], qa[3],
                    s2u(sQKV + (r0 + (lane & 15)) * STRQ + hoff + (lane >> 4) * 8));
            const int rb0 = bits3(r0 + (lane >> 2));
            const int rb1 = bits3(r0 + 8 + (lane >> 2));
            const uint32_t kaddr = s2u(sQKV + (((lane >> 4) << 3) + (lane & 7)) * STRQ
                                            + 96 + hoff + ((lane >> 3) & 1) * 8);
            const uint32_t vaddr = s2u(sQKV + (lane & 15) * STRQ + 192 + hoff + (lane >> 4) * 8);
            float o0[4] = {}, o1[4] = {}, osum[4] = {};
            #pragma unroll
            for (int jg = 0; jg < 8; jg++) {
                uint32_t kb[4];
                LDSM_X4(kb[0], kb[1], kb[2], kb[3], kaddr + jg * (16 * STRQ * 2));
                float c0[4] = {}, c1[4] = {};
                MMA_BF16(c0, qa[0], qa[1], qa[2], qa[3], kb[0], kb[1]);
                MMA_BF16(c1, qa[0], qa[1], qa[2], qa[3], kb[2], kb[3]);
                __nv_bfloat162 a0 = __floats2bfloat162_rn(ex2f(c0[0]), ex2f(c0[1]));
                __nv_bfloat162 a1 = __floats2bfloat162_rn(ex2f(c0[2]), ex2f(c0[3]));
                __nv_bfloat162 a2 = __floats2bfloat162_rn(ex2f(c1[0]), ex2f(c1[1]));
                __nv_bfloat162 a3 = __floats2bfloat162_rn(ex2f(c1[2]), ex2f(c1[3]));
                uint32_t u0 = *(uint32_t*)&a0, u1 = *(uint32_t*)&a1;
                uint32_t u2 = *(uint32_t*)&a2, u3 = *(uint32_t*)&a3;
                if (amask) {
                    int clab = ((jg >> 2) & 1) | (((jg >> 1) & 1) << 1) | wbit;
                    bool k0 = (((clab ^ rb0) & amask) == 0);
                    bool k1 = (((clab ^ rb1) & amask) == 0);
                    u0 = k0 ? u0 : 0u;  u2 = k0 ? u2 : 0u;
                    u1 = k1 ? u1 : 0u;  u3 = k1 ? u3 : 0u;
                }
                uint32_t vb[4];
                LDSM_X4_T(vb[0], vb[1], vb[2], vb[3], vaddr + jg * (16 * STRQ * 2));
                MMA_BF16(o0, u0, u1, u2, u3, vb[0], vb[1]);
                MMA_BF16(o1, u0, u1, u2, u3, vb[2], vb[3]);
                MMA_BF16(osum, u0, u1, u2, u3, ONEB, ONEB);
            }
            float inv0 = 1.0f / osum[0];
            float inv1 = 1.0f / osum[2];
            int r = r0 + (lane >> 2);
            #pragma unroll
            for (int nt = 0; nt < 2; nt++) {
                int col = hoff + nt * 8 + (lane & 3) * 2;
                float* o = nt ? o1 : o0;
                __nv_bfloat162 w0 = __floats2bfloat162_rn(o[0] * inv0, o[1] * inv0);
                __nv_bfloat162 w1 = __floats2bfloat162_rn(o[2] * inv1, o[3] * inv1);
                *(__nv_bfloat162*)(sQKV + r * STRQ + col)       = w0;
                *(__nv_bfloat162*)(sQKV + (r + 8) * STRQ + col) = w1;
            }
        }
    }
    CP_WAIT0();
    __syncthreads();

    // ---- phase 3: proj GEMM (A = attn-out q-slots, B = Wproj in pWa) -> yf ----
    {
        float acc[6][4] = {};
        #pragma unroll
        for (int ks = 0; ks < 6; ks++) {
            uint32_t a[4], bf[3][4];
            LDSM_X4(a[0], a[1], a[2], a[3], aq + ks * 32);
            #pragma unroll
            for (int ng = 0; ng < 3; ng++)
                LDSM_X4(bf[ng][0], bf[ng][1], bf[ng][2], bf[ng][3],
                        bwA + ng * (16 * 104 * 2) + ks * 32);
            #pragma unroll
            for (int nt = 0; nt < 6; nt++) {
                int ng = nt >> 1, pr = (nt & 1) * 2;
                MMA_BF16(acc[nt], a[0], a[1], a[2], a[3], bf[ng][pr], bf[ng][pr + 1]);
            }
        }
        #pragma unroll
        for (int nt = 0; nt < 6; nt++) {
            int lr = wm * 16 + (lane >> 2);
            int lc = wn * 48 + nt * 8 + (lane & 3) * 2;
            float bf0 = b_proj[lc], bf1 = b_proj[lc + 1];
            yf[lr * 148 + 48 + lc]           = acc[nt][0] + bf0;
            yf[lr * 148 + 48 + lc + 1]       = acc[nt][1] + bf1;
            yf[(lr + 8) * 148 + 48 + lc]     = acc[nt][2] + bf0;
            yf[(lr + 8) * 148 + 48 + lc + 1] = acc[nt][3] + bf1;
        }
    }
    __syncthreads();

    // ---- phase 4: y = proj + x -> GMEM scratch; LN2 -> pLN2 ----
    for (int tok = warp; tok < 128; tok += 16) {
        int dt = tok >> 6, dh = (tok >> 3) & 7, dw = tok & 7;
        int t = tb * 2 + dt, h = hb * 8 + dh, w = wb * 8 + dw;
        int ti = (t + 1) & 7, hi = (h + 4) & 127, wi = (w + 4) & 127;
        size_t m = ((size_t)((bi * 8 + ti) * 128 + hi)) * 128 + wi;
        const float* xrow = x + m * 96;
        const float* yrow = yf + tok * 148 + 48;
        float v0 = yrow[lane]      + xrow[lane];
        float v1 = yrow[lane + 32] + xrow[lane + 32];
        float v2 = yrow[lane + 64] + xrow[lane + 64];
        float* gy = yscr + m * 96;
        gy[lane]      = v0;
        gy[lane + 32] = v1;
        gy[lane + 64] = v2;
        float s  = v0 + v1 + v2;
        float s2 = v0 * v0 + v1 * v1 + v2 * v2;
        #pragma unroll
        for (int o = 16; o; o >>= 1) {
            s  += __shfl_xor_sync(0xffffffffu, s,  o);
            s2 += __shfl_xor_sync(0xffffffffu, s2, o);
        }
        float mean = s * (1.0f / 96.0f);
        float var  = s2 * (1.0f / 96.0f) - mean * mean;
        float rstd = rsqrtf(var + 1e-5f);
        __nv_bfloat16* orow = pLN2 + tok * 104;
        orow[lane]      = __float2bfloat16((v0 - mean) * rstd * g2[lane]      + b2[lane]);
        orow[lane + 32] = __float2bfloat16((v1 - mean) * rstd * g2[lane + 32] + b2[lane + 32]);
        orow[lane + 64] = __float2bfloat16((v2 - mean) * rstd * g2[lane + 64] + b2[lane + 64]);
    }
    __syncthreads();   // yf consumed -> kv region free for MLP weight buffers

    // ---- phase 5: MLP, 6 chunks of 64, double-buffered weights (cp.async) ----
    float acc2[6][4] = {};
    const uint32_t aln = s2u(pLN2 + (wm * 16 + (lane & 15)) * 104 + (lane >> 4) * 8);
    const uint32_t ah2 = s2u(sQKV + (wm * 16 + (lane & 15)) * STRQ + (lane >> 4) * 8);
    const uint32_t bw1 = s2u(sQKV + 96 + (wn * 32 + ((lane >> 4) << 3) + (lane & 7)) * STRQ
                                  + ((lane >> 3) & 1) * 8);
    const uint32_t bw2 = s2u(sQKV + 192 + (wn * 48 + ((lane >> 4) << 3) + (lane & 7)) * STRQ
                                  + ((lane >> 3) & 1) * 8);

    // prefetch W1 chunk 0
    for (int gi = tid; gi < 768; gi += 512) {
        int row = gi / 12, q = gi - (gi / 12) * 12;
        CP_ASYNC16(s2u(sQKV + row * STRQ + 96 + q * 8),
                   (const void*)(w1 + (size_t)row * 96 + q * 8));
    }
    CP_COMMIT();

    for (int c = 0; c < 6; c++) {
        CP_WAIT0();
        __syncthreads();   // W1c ready; hidden free (prev fc2 done)
        // prefetch W2 chunk c -> bufW2
        for (int gi = tid; gi < 768; gi += 512) {
            int row = gi >> 3, q = gi & 7;
            CP_ASYNC16(s2u(sQKV + row * STRQ + 192 + q * 8),
                       (const void*)(w2 + (size_t)row * 384 + c * 64 + q * 8));
        }
        CP_COMMIT();
        // fc1 chunk: (128x96)@(64x96)^T + bias + GELU -> hidden (q-slots cols 0..63)
        {
            float a1[4][4] = {};
            #pragma unroll
            for (int ks = 0; ks < 6; ks++) {
                uint32_t a[4], bf[2][4];
                LDSM_X4(a[0], a[1], a[2], a[3], aln + ks * 32);
                #pragma unroll
                for (int ng = 0; ng < 2; ng++)
                    LDSM_X4(bf[ng][0], bf[ng][1], bf[ng][2], bf[ng][3],
                            bw1 + ng * (16 * STRQ * 2) + ks * 32);
                #pragma unroll
                for (int nt = 0; nt < 4; nt++) {
                    int ng = nt >> 1, pr = (nt & 1) * 2;
                    MMA_BF16(a1[nt], a[0], a[1], a[2], a[3], bf[ng][pr], bf[ng][pr + 1]);
                }
            }
            #pragma unroll
            for (int nt = 0; nt < 4; nt++) {
                int lr = wm * 16 + (lane >> 2);
                int lc = wn * 32 + nt * 8 + (lane & 3) * 2;
                int gcol = c * 64 + lc;
                float bf0 = bias1[gcol], bf1 = bias1[gcol + 1];
                float v0 = gelu_t(a1[nt][0] + bf0);
                float v1 = gelu_t(a1[nt][1] + bf1);
                float v2 = gelu_t(a1[nt][2] + bf0);
                float v3 = gelu_t(a1[nt][3] + bf1);
                __nv_bfloat162 p0, p1;
                p0.x = __float2bfloat16(v0); p0.y = __float2bfloat16(v1);
                p1.x = __float2bfloat16(v2); p1.y = __float2bfloat16(v3);
                *(__nv_bfloat162*)(sQKV + lr * STRQ + lc)       = p0;
                *(__nv_bfloat162*)(sQKV + (lr + 8) * STRQ + lc) = p1;
            }
        }
        CP_WAIT0();
        __syncthreads();   // W2c ready; hidden ready; bufW1 free
        // prefetch W1 chunk c+1 -> bufW1 (overlaps fc2)
        if (c < 5) {
            for (int gi = tid; gi < 768; gi += 512) {
                int row = gi / 12, q = gi - (gi / 12) * 12;
                CP_ASYNC16(s2u(sQKV + row * STRQ + 96 + q * 8),
                           (const void*)(w1 + (size_t)((c + 1) * 64 + row) * 96 + q * 8));
            }
        }
        CP_COMMIT();
        // fc2 partial: (128x64)@(96x64)^T accumulate
        #pragma unroll
        for (int ks = 0; ks < 4; ks++) {
            uint32_t a[4], bf[3][4];
            LDSM_X4(a[0], a[1], a[2], a[3], ah2 + ks * 32);
            #pragma unroll
            for (int ng = 0; ng < 3; ng++)
                LDSM_X4(bf[ng][0], bf[ng][1], bf[ng][2], bf[ng][3],
                        bw2 + ng * (16 * STRQ * 2) + ks * 32);
            #pragma unroll
            for (int nt = 0; nt < 6; nt++) {
                int ng = nt >> 1, pr = (nt & 1) * 2;
                MMA_BF16(acc2[nt], a[0], a[1], a[2], a[3], bf[ng][pr], bf[ng][pr + 1]);
            }
        }
    }

    // ---- phase 6: out = fc2 + bias2 + y(gmem), scatter natural order (fp32) ----
    #pragma unroll
    for (int hh = 0; hh < 2; hh++) {
        int lr = wm * 16 + (lane >> 2) + hh * 8;
        int dt = lr >> 6, dh = (lr >> 3) & 7, dw = lr & 7;
        int t = tb * 2 + dt, h = hb * 8 + dh, w = wb * 8 + dw;
        int ti = (t + 1) & 7, hi = (h + 4) & 127, wi = (w + 4) & 127;
        size_t m = ((size_t)((bi * 8 + ti) * 128 + hi)) * 128 + wi;
        #pragma unroll
        for (int nt = 0; nt < 6; nt++) {
            int lc = wn * 48 + nt * 8 + (lane & 3) * 2;
            float2 yv = *(const float2*)(yscr + m * 96 + lc);
            float v0 = acc2[nt][hh * 2 + 0] + bias2[lc]     + yv.x;
            float v1 = acc2[nt][hh * 2 + 1] + bias2[lc + 1] + yv.y;
            *(float2*)(out + m * 96 + lc) = make_float2(v0, v1);
        }
    }
}

// ---------------- launch ----------------
extern "C" void kernel_launch(void* const* d_in, const int* in_sizes, int n_in,
                              void* d_out, int out_size)
{
    const float* x      = (const float*)d_in[0];
    const float* g1     = (const float*)d_in[2];
    const float* b1     = (const float*)d_in[3];
    const float* w_qkv  = (const float*)d_in[4];
    const float* b_qkv  = (const float*)d_in[5];
    const float* w_proj = (const float*)d_in[6];
    const float* b_proj = (const float*)d_in[7];
    const float* g2     = (const float*)d_in[8];
    const float* b2     = (const float*)d_in[9];
    const float* w_fc1  = (const float*)d_in[10];
    const float* b_fc1  = (const float*)d_in[11];
    const float* w_fc2  = (const float*)d_in[12];
    const float* b_fc2  = (const float*)d_in[13];
    float* out = (float*)d_out;

    __nv_bfloat16 *p_wb;
    float *p_y;
    cudaGetSymbolAddress((void**)&p_wb, g_wb);
    cudaGetSymbolAddress((void**)&p_y,  g_y);

    static bool attr_set = false;
    if (!attr_set) {
        cudaFuncSetAttribute(mono_kernel,
                             cudaFuncAttributeMaxDynamicSharedMemorySize, SMEM_MONO);
        attr_set = true;
    }

    convert_w<<<(110592 + 255) / 256, 256>>>(w_qkv, w_proj, w_fc1, w_fc2, p_wb);

    mono_kernel<<<NWIN, 512, SMEM_MONO>>>(
        x, g1, b1,
        p_wb + WB_QKV, b_qkv, p_wb + WB_PROJ, b_proj,
        g2, b2,
        p_wb + WB_FC1, b_fc1, p_wb + WB_FC2, b_fc2,
        p_y, out);
}

// round 16
// speedup vs baseline: 1.3941x; 1.0003x over previous
#include <cuda_runtime.h>
#include <cuda_bf16.h>
#include <math.h>
#include <stdint.h>

// ---------------- problem constants ----------------
#define NTOK (2*8*128*128)          // 262144 tokens
#define NWIN (NTOK/128)             // 2048 windows
// SCALE * log2(e) folded into q at QKV epilogue:
#define QSCALE 0.36067376022224085f

// ---------------- scratch ----------------
__device__ __nv_bfloat16 g_wb [110592];              // bf16 weights
__device__ float         g_y  [(size_t)NTOK * 96];   // first residual (natural, fp32)

#define WB_QKV  0
#define WB_PROJ 27648
#define WB_FC1  36864
#define WB_FC2  73728

static __device__ __forceinline__ uint32_t s2u(const void* p) {
    return (uint32_t)__cvta_generic_to_shared(p);
}

#define LDSM_X4(r0,r1,r2,r3,addr) \
    asm volatile("ldmatrix.sync.aligned.m8n8.x4.shared.b16 {%0,%1,%2,%3}, [%4];" \
        : "=r"(r0),"=r"(r1),"=r"(r2),"=r"(r3) : "r"(addr))

#define LDSM_X4_T(r0,r1,r2,r3,addr) \
    asm volatile("ldmatrix.sync.aligned.m8n8.x4.trans.shared.b16 {%0,%1,%2,%3}, [%4];" \
        : "=r"(r0),"=r"(r1),"=r"(r2),"=r"(r3) : "r"(addr))

#define MMA_BF16(c,a0,a1,a2,a3,b0,b1) \
    asm volatile("mma.sync.aligned.m16n8k16.row.col.f32.bf16.bf16.f32 " \
        "{%0,%1,%2,%3},{%4,%5,%6,%7},{%8,%9},{%0,%1,%2,%3};" \
        : "+f"(c[0]),"+f"(c[1]),"+f"(c[2]),"+f"(c[3]) \
        : "r"(a0),"r"(a1),"r"(a2),"r"(a3),"r"(b0),"r"(b1))

#define CP_ASYNC16(dst,src) \
    asm volatile("cp.async.cg.shared.global [%0], [%1], 16;" :: "r"(dst), "l"(src))
#define CP_COMMIT() asm volatile("cp.async.commit_group;")
#define CP_WAIT0()  asm volatile("cp.async.wait_group 0;")

static __device__ __forceinline__ float ex2f(float x) {
    float r;
    asm("ex2.approx.f32 %0, %1;" : "=f"(r) : "f"(x));
    return r;
}

static __device__ __forceinline__ float gelu_t(float v) {
    float u = 0.7978845608028654f * v * fmaf(0.044715f, v * v, 1.0f);
    float t;
    asm("tanh.approx.f32 %0, %1;" : "=f"(t) : "f"(u));
    return 0.5f * v * (1.0f + t);
}

// label bits of token n: {t: bit6, h: bit5, w: bit2}
static __device__ __forceinline__ int bits3(int n) {
    return ((n >> 6) & 1) | (((n >> 5) & 1) << 1) | (((n >> 2) & 1) << 2);
}

// ---------------- weight conversion fp32 -> bf16 ----------------
__global__ void convert_w(const float* __restrict__ wq, const float* __restrict__ wp,
                          const float* __restrict__ w1, const float* __restrict__ w2,
                          __nv_bfloat16* __restrict__ out)
{
    int i = blockIdx.x * 256 + threadIdx.x;
    if (i < 27648)       out[i] = __float2bfloat16(wq[i]);
    else if (i < 36864)  out[i] = __float2bfloat16(wp[i - 27648]);
    else if (i < 73728)  out[i] = __float2bfloat16(w1[i - 36864]);
    else if (i < 110592) out[i] = __float2bfloat16(w2[i - 73728]);
}

// ================= MONO kernel, 512 threads, 2 CTAs/SM =================
// smem (bf16 elems):
//   sQKV [0, 37888)      128x296: q-slots cols 0..95, kv-slots cols 96..287
//   pWa  [37888, 47872)  weight buffer (96x104)  -- k, then q, then Wproj
//   pLN2 [43264, 56576)  LN2 tile 128x104 (phase >= 4 only; pWa dead by then)
// v-chunk weights stage temporarily in the v-slots (cols 192..287) of sQKV.
#define STRQ 296
#define OFF_WA  37888
#define OFF_LN2 43264
#define SMEM_MONO 113664

__global__ __launch_bounds__(512, 2) void mono_kernel(
    const float* __restrict__ x,
    const float* __restrict__ g1, const float* __restrict__ b1,
    const __nv_bfloat16* __restrict__ wqkv, const float* __restrict__ b_qkv,
    const __nv_bfloat16* __restrict__ wproj, const float* __restrict__ b_proj,
    const float* __restrict__ g2, const float* __restrict__ b2,
    const __nv_bfloat16* __restrict__ w1, const float* __restrict__ bias1,
    const __nv_bfloat16* __restrict__ w2, const float* __restrict__ bias2,
    float* __restrict__ yscr,
    float* __restrict__ out)
{
    extern __shared__ __align__(16) char smem_raw[];
    __nv_bfloat16* sQKV = (__nv_bfloat16*)smem_raw;
    __nv_bfloat16* pWa  = sQKV + OFF_WA;
    __nv_bfloat16* pLN2 = sQKV + OFF_LN2;
    float* yf = (float*)smem_raw;       // y staging: yf[row*148 + 48 + col]

    const int tid  = threadIdx.x;
    const int lane = tid & 31;
    const int warp = tid >> 5;        // 16 warps
    const int wm = warp & 7, wn = warp >> 3;   // 8m x 2n

    const int win = blockIdx.x;
    const int wr = win & 1023;
    const int tb = wr >> 8, hb = (wr >> 4) & 15, wb = wr & 15;
    const int bi = win >> 10;
    const int amask = ((tb == 3) ? 1 : 0) | ((hb == 15) ? 2 : 0) | ((wb == 15) ? 4 : 0);

    // ---- phase 0: prefetch k-chunk weights -> pWa + LN1 (shift gather) ----
    for (int gi = tid; gi < 1152; gi += 512) {
        int row = gi / 12, q = gi - row * 12;
        CP_ASYNC16(s2u(pWa + row * 104 + q * 8),
                   (const void*)(wqkv + (size_t)(96 + row) * 96 + q * 8));
    }
    CP_COMMIT();

    for (int tok = warp; tok < 128; tok += 16) {
        int dt = tok >> 6, dh = (tok >> 3) & 7, dw = tok & 7;
        int t = tb * 2 + dt, h = hb * 8 + dh, w = wb * 8 + dw;
        int ti = (t + 1) & 7, hi = (h + 4) & 127, wi = (w + 4) & 127;
        size_t src = ((size_t)((bi * 8 + ti) * 128 + hi)) * 128 + wi;
        const float* row = x + src * 96;
        float v0 = row[lane], v1 = row[lane + 32], v2 = row[lane + 64];
        float s  = v0 + v1 + v2;
        float s2 = v0 * v0 + v1 * v1 + v2 * v2;
        #pragma unroll
        for (int o = 16; o; o >>= 1) {
            s  += __shfl_xor_sync(0xffffffffu, s,  o);
            s2 += __shfl_xor_sync(0xffffffffu, s2, o);
        }
        float mean = s * (1.0f / 96.0f);
        float var  = s2 * (1.0f / 96.0f) - mean * mean;
        float rstd = rsqrtf(var + 1e-5f);
        __nv_bfloat16* orow = sQKV + tok * STRQ;
        orow[lane]      = __float2bfloat16((v0 - mean) * rstd * g1[lane]      + b1[lane]);
        orow[lane + 32] = __float2bfloat16((v1 - mean) * rstd * g1[lane + 32] + b1[lane + 32]);
        orow[lane + 64] = __float2bfloat16((v2 - mean) * rstd * g1[lane + 64] + b1[lane + 64]);
    }

    // ---- phase 1: QKV GEMM (k, v, q), loads overlapped ----
    const uint32_t aq = s2u(sQKV + (wm * 16 + (lane & 15)) * STRQ + (lane >> 4) * 8);
    const uint32_t bwA = s2u(pWa + (wn * 48 + ((lane >> 4) << 3) + (lane & 7)) * 104
                                 + ((lane >> 3) & 1) * 8);
    // v-chunk weights staged in v-slots: row stride STRQ, base col 192
    const uint32_t bwV = s2u(sQKV + (wn * 48 + ((lane >> 4) << 3) + (lane & 7)) * STRQ
                                  + 192 + ((lane >> 3) & 1) * 8);

    // -- chunk k (weights in pWa) --
    {
        CP_WAIT0();
        __syncthreads();   // k weights + LN1 visible
        // prefetch v weights into the (empty) v-slots
        for (int gi = tid; gi < 1152; gi += 512) {
            int row = gi / 12, q = gi - row * 12;
            CP_ASYNC16(s2u(sQKV + row * STRQ + 192 + q * 8),
                       (const void*)(wqkv + (size_t)(192 + row) * 96 + q * 8));
        }
        CP_COMMIT();

        float acc[6][4] = {};
        #pragma unroll
        for (int ks = 0; ks < 6; ks++) {
            uint32_t a[4], bf[3][4];
            LDSM_X4(a[0], a[1], a[2], a[3], aq + ks * 32);
            #pragma unroll
            for (int ng = 0; ng < 3; ng++)
                LDSM_X4(bf[ng][0], bf[ng][1], bf[ng][2], bf[ng][3],
                        bwA + ng * (16 * 104 * 2) + ks * 32);
            #pragma unroll
            for (int nt = 0; nt < 6; nt++) {
                int ng = nt >> 1, pr = (nt & 1) * 2;
                MMA_BF16(acc[nt], a[0], a[1], a[2], a[3], bf[ng][pr], bf[ng][pr + 1]);
            }
        }
        #pragma unroll
        for (int nt = 0; nt < 6; nt++) {
            int lr = wm * 16 + (lane >> 2);
            int lc = wn * 48 + nt * 8 + (lane & 3) * 2;
            int gcol = 96 + lc;                       // k -> cols 96..191
            float bf0 = b_qkv[gcol], bf1 = b_qkv[gcol + 1];
            __nv_bfloat162 p0, p1;
            p0.x = __float2bfloat16(acc[nt][0] + bf0);
            p0.y = __float2bfloat16(acc[nt][1] + bf1);
            p1.x = __float2bfloat16(acc[nt][2] + bf0);
            p1.y = __float2bfloat16(acc[nt][3] + bf1);
            *(__nv_bfloat162*)(sQKV + lr * STRQ + gcol)       = p0;
            *(__nv_bfloat162*)(sQKV + (lr + 8) * STRQ + gcol) = p1;
        }
    }

    // -- chunk v (weights in v-slots) --
    {
        CP_WAIT0();
        __syncthreads();   // v weights visible; all warps done reading pWa (k)
        // prefetch q weights into pWa
        for (int gi = tid; gi < 1152; gi += 512) {
            int row = gi / 12, q = gi - row * 12;
            CP_ASYNC16(s2u(pWa + row * 104 + q * 8),
                       (const void*)(wqkv + (size_t)row * 96 + q * 8));
        }
        CP_COMMIT();

        float acc[6][4] = {};
        #pragma unroll
        for (int ks = 0; ks < 6; ks++) {
            uint32_t a[4], bf[3][4];
            LDSM_X4(a[0], a[1], a[2], a[3], aq + ks * 32);
            #pragma unroll
            for (int ng = 0; ng < 3; ng++)
                LDSM_X4(bf[ng][0], bf[ng][1], bf[ng][2], bf[ng][3],
                        bwV + ng * (16 * STRQ * 2) + ks * 32);
            #pragma unroll
            for (int nt = 0; nt < 6; nt++) {
                int ng = nt >> 1, pr = (nt & 1) * 2;
                MMA_BF16(acc[nt], a[0], a[1], a[2], a[3], bf[ng][pr], bf[ng][pr + 1]);
            }
        }
        __syncthreads();   // all warps done reading v-slot weights before overwrite
        #pragma unroll
        for (int nt = 0; nt < 6; nt++) {
            int lr = wm * 16 + (lane >> 2);
            int lc = wn * 48 + nt * 8 + (lane & 3) * 2;
            int gcol = 192 + lc;                      // v -> cols 192..287
            float bf0 = b_qkv[gcol], bf1 = b_qkv[gcol + 1];
            __nv_bfloat162 p0, p1;
            p0.x = __float2bfloat16(acc[nt][0] + bf0);
            p0.y = __float2bfloat16(acc[nt][1] + bf1);
            p1.x = __float2bfloat16(acc[nt][2] + bf0);
            p1.y = __float2bfloat16(acc[nt][3] + bf1);
            *(__nv_bfloat162*)(sQKV + lr * STRQ + gcol)       = p0;
            *(__nv_bfloat162*)(sQKV + (lr + 8) * STRQ + gcol) = p1;
        }
    }

    // -- chunk q (weights in pWa; output pre-scaled by QSCALE) --
    {
        CP_WAIT0();
        __syncthreads();   // q weights visible
        float acc[6][4] = {};
        #pragma unroll
        for (int ks = 0; ks < 6; ks++) {
            uint32_t a[4], bf[3][4];
            LDSM_X4(a[0], a[1], a[2], a[3], aq + ks * 32);
            #pragma unroll
            for (int ng = 0; ng < 3; ng++)
                LDSM_X4(bf[ng][0], bf[ng][1], bf[ng][2], bf[ng][3],
                        bwA + ng * (16 * 104 * 2) + ks * 32);
            #pragma unroll
            for (int nt = 0; nt < 6; nt++) {
                int ng = nt >> 1, pr = (nt & 1) * 2;
                MMA_BF16(acc[nt], a[0], a[1], a[2], a[3], bf[ng][pr], bf[ng][pr + 1]);
            }
        }
        __syncthreads();   // all warps done reading LN1 (q-slots)
        #pragma unroll
        for (int nt = 0; nt < 6; nt++) {
            int lr = wm * 16 + (lane >> 2);
            int lc = wn * 48 + nt * 8 + (lane & 3) * 2;
            float bf0 = b_qkv[lc], bf1 = b_qkv[lc + 1];
            __nv_bfloat162 p0, p1;
            p0.x = __float2bfloat16((acc[nt][0] + bf0) * QSCALE);
            p0.y = __float2bfloat16((acc[nt][1] + bf1) * QSCALE);
            p1.x = __float2bfloat16((acc[nt][2] + bf0) * QSCALE);
            p1.y = __float2bfloat16((acc[nt][3] + bf1) * QSCALE);
            *(__nv_bfloat162*)(sQKV + lr * STRQ + lc)       = p0;
            *(__nv_bfloat162*)(sQKV + (lr + 8) * STRQ + lc) = p1;
        }
    }
    __syncthreads();

    // ---- phase 2: attention + Wproj prefetch into pWa ----
    for (int gi = tid; gi < 1152; gi += 512) {
        int row = gi / 12, q = gi - row * 12;
        CP_ASYNC16(s2u(pWa + row * 104 + q * 8),
                   (const void*)(wproj + (size_t)row * 96 + q * 8));
    }
    CP_COMMIT();
    {
        const uint32_t ONEB = 0x3F803F80u;   // bf16x2 {1.0, 1.0}
        const int wbit = ((lane >> 1) & 1) << 2;   // column w-label bit (per lane)
        for (int u = warp; u < 48; u += 16) {
            int head = u >> 3, rtile = u & 7;
            int hoff = head * 16, r0 = rtile * 16;
            uint32_t qa[4];
            LDSM_X4(qa[0], qa[1], qa[2], qa[3],
                    s2u(sQKV + (r0 + (lane & 15)) * STRQ + hoff + (lane >> 4) * 8));
            const int rb0 = bits3(r0 + (lane >> 2));
            const int rb1 = bits3(r0 + 8 + (lane >> 2));
            const uint32_t kaddr = s2u(sQKV + (((lane >> 4) << 3) + (lane & 7)) * STRQ
                                            + 96 + hoff + ((lane >> 3) & 1) * 8);
            const uint32_t vaddr = s2u(sQKV + (lane & 15) * STRQ + 192 + hoff + (lane >> 4) * 8);
            float o0[4] = {}, o1[4] = {}, osum[4] = {};
            #pragma unroll
            for (int jg = 0; jg < 8; jg++) {
                uint32_t kb[4];
                LDSM_X4(kb[0], kb[1], kb[2], kb[3], kaddr + jg * (16 * STRQ * 2));
                float c0[4] = {}, c1[4] = {};
                MMA_BF16(c0, qa[0], qa[1], qa[2], qa[3], kb[0], kb[1]);
                MMA_BF16(c1, qa[0], qa[1], qa[2], qa[3], kb[2], kb[3]);
                __nv_bfloat162 a0 = __floats2bfloat162_rn(ex2f(c0[0]), ex2f(c0[1]));
                __nv_bfloat162 a1 = __floats2bfloat162_rn(ex2f(c0[2]), ex2f(c0[3]));
                __nv_bfloat162 a2 = __floats2bfloat162_rn(ex2f(c1[0]), ex2f(c1[1]));
                __nv_bfloat162 a3 = __floats2bfloat162_rn(ex2f(c1[2]), ex2f(c1[3]));
                uint32_t u0 = *(uint32_t*)&a0, u1 = *(uint32_t*)&a1;
                uint32_t u2 = *(uint32_t*)&a2, u3 = *(uint32_t*)&a3;
                if (amask) {
                    int clab = ((jg >> 2) & 1) | (((jg >> 1) & 1) << 1) | wbit;
                    bool k0 = (((clab ^ rb0) & amask) == 0);
                    bool k1 = (((clab ^ rb1) & amask) == 0);
                    u0 = k0 ? u0 : 0u;  u2 = k0 ? u2 : 0u;
                    u1 = k1 ? u1 : 0u;  u3 = k1 ? u3 : 0u;
                }
                uint32_t vb[4];
                LDSM_X4_T(vb[0], vb[1], vb[2], vb[3], vaddr + jg * (16 * STRQ * 2));
                MMA_BF16(o0, u0, u1, u2, u3, vb[0], vb[1]);
                MMA_BF16(o1, u0, u1, u2, u3, vb[2], vb[3]);
                MMA_BF16(osum, u0, u1, u2, u3, ONEB, ONEB);
            }
            float inv0 = 1.0f / osum[0];
            float inv1 = 1.0f / osum[2];
            int r = r0 + (lane >> 2);
            #pragma unroll
            for (int nt = 0; nt < 2; nt++) {
                int col = hoff + nt * 8 + (lane & 3) * 2;
                float* o = nt ? o1 : o0;
                __nv_bfloat162 w0 = __floats2bfloat162_rn(o[0] * inv0, o[1] * inv0);
                __nv_bfloat162 w1 = __floats2bfloat162_rn(o[2] * inv1, o[3] * inv1);
                *(__nv_bfloat162*)(sQKV + r * STRQ + col)       = w0;
                *(__nv_bfloat162*)(sQKV + (r + 8) * STRQ + col) = w1;
            }
        }
    }
    CP_WAIT0();
    __syncthreads();

    // ---- phase 3: proj GEMM (A = attn-out q-slots, B = Wproj in pWa) -> yf ----
    {
        float acc[6][4] = {};
        #pragma unroll
        for (int ks = 0; ks < 6; ks++) {
            uint32_t a[4], bf[3][4];
            LDSM_X4(a[0], a[1], a[2], a[3], aq + ks * 32);
            #pragma unroll
            for (int ng = 0; ng < 3; ng++)
                LDSM_X4(bf[ng][0], bf[ng][1], bf[ng][2], bf[ng][3],
                        bwA + ng * (16 * 104 * 2) + ks * 32);
            #pragma unroll
            for (int nt = 0; nt < 6; nt++) {
                int ng = nt >> 1, pr = (nt & 1) * 2;
                MMA_BF16(acc[nt], a[0], a[1], a[2], a[3], bf[ng][pr], bf[ng][pr + 1]);
            }
        }
        #pragma unroll
        for (int nt = 0; nt < 6; nt++) {
            int lr = wm * 16 + (lane >> 2);
            int lc = wn * 48 + nt * 8 + (lane & 3) * 2;
            float bf0 = b_proj[lc], bf1 = b_proj[lc + 1];
            yf[lr * 148 + 48 + lc]           = acc[nt][0] + bf0;
            yf[lr * 148 + 48 + lc + 1]       = acc[nt][1] + bf1;
            yf[(lr + 8) * 148 + 48 + lc]     = acc[nt][2] + bf0;
            yf[(lr + 8) * 148 + 48 + lc + 1] = acc[nt][3] + bf1;
        }
    }
    __syncthreads();

    // ---- phase 4: y = proj + x -> GMEM scratch; LN2 -> pLN2 ----
    for (int tok = warp; tok < 128; tok += 16) {
        int dt = tok >> 6, dh = (tok >> 3) & 7, dw = tok & 7;
        int t = tb * 2 + dt, h = hb * 8 + dh, w = wb * 8 + dw;
        int ti = (t + 1) & 7, hi = (h + 4) & 127, wi = (w + 4) & 127;
        size_t m = ((size_t)((bi * 8 + ti) * 128 + hi)) * 128 + wi;
        const float* xrow = x + m * 96;
        const float* yrow = yf + tok * 148 + 48;
        float v0 = yrow[lane]      + xrow[lane];
        float v1 = yrow[lane + 32] + xrow[lane + 32];
        float v2 = yrow[lane + 64] + xrow[lane + 64];
        float* gy = yscr + m * 96;
        gy[lane]      = v0;
        gy[lane + 32] = v1;
        gy[lane + 64] = v2;
        float s  = v0 + v1 + v2;
        float s2 = v0 * v0 + v1 * v1 + v2 * v2;
        #pragma unroll
        for (int o = 16; o; o >>= 1) {
            s  += __shfl_xor_sync(0xffffffffu, s,  o);
            s2 += __shfl_xor_sync(0xffffffffu, s2, o);
        }
        float mean = s * (1.0f / 96.0f);
        float var  = s2 * (1.0f / 96.0f) - mean * mean;
        float rstd = rsqrtf(var + 1e-5f);
        __nv_bfloat16* orow = pLN2 + tok * 104;
        orow[lane]      = __float2bfloat16((v0 - mean) * rstd * g2[lane]      + b2[lane]);
        orow[lane + 32] = __float2bfloat16((v1 - mean) * rstd * g2[lane + 32] + b2[lane + 32]);
        orow[lane + 64] = __float2bfloat16((v2 - mean) * rstd * g2[lane + 64] + b2[lane + 64]);
    }
    __syncthreads();   // yf consumed -> kv region free for MLP weight buffers

    // ---- phase 5: MLP, 6 chunks of 64, double-buffered weights (cp.async) ----
    float acc2[6][4] = {};
    const uint32_t aln = s2u(pLN2 + (wm * 16 + (lane & 15)) * 104 + (lane >> 4) * 8);
    const uint32_t ah2 = s2u(sQKV + (wm * 16 + (lane & 15)) * STRQ + (lane >> 4) * 8);
    const uint32_t bw1 = s2u(sQKV + 96 + (wn * 32 + ((lane >> 4) << 3) + (lane & 7)) * STRQ
                                  + ((lane >> 3) & 1) * 8);
    const uint32_t bw2 = s2u(sQKV + 192 + (wn * 48 + ((lane >> 4) << 3) + (lane & 7)) * STRQ
                                  + ((lane >> 3) & 1) * 8);

    // prefetch W1 chunk 0
    for (int gi = tid; gi < 768; gi += 512) {
        int row = gi / 12, q = gi - (gi / 12) * 12;
        CP_ASYNC16(s2u(sQKV + row * STRQ + 96 + q * 8),
                   (const void*)(w1 + (size_t)row * 96 + q * 8));
    }
    CP_COMMIT();

    for (int c = 0; c < 6; c++) {
        CP_WAIT0();
        __syncthreads();   // W1c ready; hidden free (prev fc2 done)
        // prefetch W2 chunk c -> bufW2
        for (int gi = tid; gi < 768; gi += 512) {
            int row = gi >> 3, q = gi & 7;
            CP_ASYNC16(s2u(sQKV + row * STRQ + 192 + q * 8),
                       (const void*)(w2 + (size_t)row * 384 + c * 64 + q * 8));
        }
        CP_COMMIT();
        // fc1 chunk: (128x96)@(64x96)^T + bias + GELU -> hidden (q-slots cols 0..63)
        {
            float a1[4][4] = {};
            #pragma unroll
            for (int ks = 0; ks < 6; ks++) {
                uint32_t a[4], bf[2][4];
                LDSM_X4(a[0], a[1], a[2], a[3], aln + ks * 32);
                #pragma unroll
                for (int ng = 0; ng < 2; ng++)
                    LDSM_X4(bf[ng][0], bf[ng][1], bf[ng][2], bf[ng][3],
                            bw1 + ng * (16 * STRQ * 2) + ks * 32);
                #pragma unroll
                for (int nt = 0; nt < 4; nt++) {
                    int ng = nt >> 1, pr = (nt & 1) * 2;
                    MMA_BF16(a1[nt], a[0], a[1], a[2], a[3], bf[ng][pr], bf[ng][pr + 1]);
                }
            }
            #pragma unroll
            for (int nt = 0; nt < 4; nt++) {
                int lr = wm * 16 + (lane >> 2);
                int lc = wn * 32 + nt * 8 + (lane & 3) * 2;
                int gcol = c * 64 + lc;
                float bf0 = bias1[gcol], bf1 = bias1[gcol + 1];
                float v0 = gelu_t(a1[nt][0] + bf0);
                float v1 = gelu_t(a1[nt][1] + bf1);
                float v2 = gelu_t(a1[nt][2] + bf0);
                float v3 = gelu_t(a1[nt][3] + bf1);
                __nv_bfloat162 p0, p1;
                p0.x = __float2bfloat16(v0); p0.y = __float2bfloat16(v1);
                p1.x = __float2bfloat16(v2); p1.y = __float2bfloat16(v3);
                *(__nv_bfloat162*)(sQKV + lr * STRQ + lc)       = p0;
                *(__nv_bfloat162*)(sQKV + (lr + 8) * STRQ + lc) = p1;
            }
        }
        CP_WAIT0();
        __syncthreads();   // W2c ready; hidden ready; bufW1 free
        // prefetch W1 chunk c+1 -> bufW1 (overlaps fc2)
        if (c < 5) {
            for (int gi = tid; gi < 768; gi += 512) {
                int row = gi / 12, q = gi - (gi / 12) * 12;
                CP_ASYNC16(s2u(sQKV + row * STRQ + 96 + q * 8),
                           (const void*)(w1 + (size_t)((c + 1) * 64 + row) * 96 + q * 8));
            }
        }
        CP_COMMIT();
        // fc2 partial: (128x64)@(96x64)^T accumulate
        #pragma unroll
        for (int ks = 0; ks < 4; ks++) {
            uint32_t a[4], bf[3][4];
            LDSM_X4(a[0], a[1], a[2], a[3], ah2 + ks * 32);
            #pragma unroll
            for (int ng = 0; ng < 3; ng++)
                LDSM_X4(bf[ng][0], bf[ng][1], bf[ng][2], bf[ng][3],
                        bw2 + ng * (16 * STRQ * 2) + ks * 32);
            #pragma unroll
            for (int nt = 0; nt < 6; nt++) {
                int ng = nt >> 1, pr = (nt & 1) * 2;
                MMA_BF16(acc2[nt], a[0], a[1], a[2], a[3], bf[ng][pr], bf[ng][pr + 1]);
            }
        }
    }

    // ---- phase 6: out = fc2 + bias2 + y(gmem), scatter natural order (fp32) ----
    #pragma unroll
    for (int hh = 0; hh < 2; hh++) {
        int lr = wm * 16 + (lane >> 2) + hh * 8;
        int dt = lr >> 6, dh = (lr >> 3) & 7, dw = lr & 7;
        int t = tb * 2 + dt, h = hb * 8 + dh, w = wb * 8 + dw;
        int ti = (t + 1) & 7, hi = (h + 4) & 127, wi = (w + 4) & 127;
        size_t m = ((size_t)((bi * 8 + ti) * 128 + hi)) * 128 + wi;
        #pragma unroll
        for (int nt = 0; nt < 6; nt++) {
            int lc = wn * 48 + nt * 8 + (lane & 3) * 2;
            float2 yv = *(const float2*)(yscr + m * 96 + lc);
            float v0 = acc2[nt][hh * 2 + 0] + bias2[lc]     + yv.x;
            float v1 = acc2[nt][hh * 2 + 1] + bias2[lc + 1] + yv.y;
            *(float2*)(out + m * 96 + lc) = make_float2(v0, v1);
        }
    }
}

// ---------------- launch ----------------
extern "C" void kernel_launch(void* const* d_in, const int* in_sizes, int n_in,
                              void* d_out, int out_size)
{
    const float* x      = (const float*)d_in[0];
    const float* g1     = (const float*)d_in[2];
    const float* b1     = (const float*)d_in[3];
    const float* w_qkv  = (const float*)d_in[4];
    const float* b_qkv  = (const float*)d_in[5];
    const float* w_proj = (const float*)d_in[6];
    const float* b_proj = (const float*)d_in[7];
    const float* g2     = (const float*)d_in[8];
    const float* b2     = (const float*)d_in[9];
    const float* w_fc1  = (const float*)d_in[10];
    const float* b_fc1  = (const float*)d_in[11];
    const float* w_fc2  = (const float*)d_in[12];
    const float* b_fc2  = (const float*)d_in[13];
    float* out = (float*)d_out;

    __nv_bfloat16 *p_wb;
    float *p_y;
    cudaGetSymbolAddress((void**)&p_wb, g_wb);
    cudaGetSymbolAddress((void**)&p_y,  g_y);

    static bool attr_set = false;
    if (!attr_set) {
        cudaFuncSetAttribute(mono_kernel,
                             cudaFuncAttributeMaxDynamicSharedMemorySize, SMEM_MONO);
        attr_set = true;
    }

    convert_w<<<(110592 + 255) / 256, 256>>>(w_qkv, w_proj, w_fc1, w_fc2, p_wb);

    mono_kernel<<<NWIN, 512, SMEM_MONO>>>(
        x, g1, b1,
        p_wb + WB_QKV, b_qkv, p_wb + WB_PROJ, b_proj,
        g2, b2,
        p_wb + WB_FC1, b_fc1, p_wb + WB_FC2, b_fc2,
        p_y, out);
}